// round 10
// baseline (speedup 1.0000x reference)
#include <cuda_runtime.h>
#include <math.h>

// Problem dims
#define SEQ   256
#define BATCH 64
#define IDIM  1024
#define HDIM  1024
#define PLEN  256
#define PDIM  1024

#define RBLOCKS  256
#define RTHREADS 256

// -------- device scratch (no runtime allocation allowed) --------
__device__ __align__(16) float g_gi[SEQ * BATCH * 3 * HDIM];   // precomputed input gates
__device__ __align__(16) float g_h2[2 * BATCH * HDIM];         // double-buffered hidden state
__device__ float g_query[SEQ * BATCH * PDIM];
__device__ float g_scores[BATCH * SEQ * PLEN];
__device__ float g_attn[BATCH * SEQ * PLEN];
__device__ __align__(16) float2 g_Whh2[3 * HDIM * HDIM];       // pre-split W_hh (hi,lo), block-ordered+permuted
__device__ unsigned g_bar;                                     // grid barrier counter

// =====================================================================
// helpers
// =====================================================================
__device__ __forceinline__ void cp_async16(void* smem_dst, const void* gmem_src)
{
    unsigned ds = (unsigned)__cvta_generic_to_shared(smem_dst);
    asm volatile("cp.async.cg.shared.global [%0], [%1], 16;\n" :: "r"(ds), "l"(gmem_src));
}

__device__ __forceinline__ unsigned f2tf(float x)
{
    unsigned r; asm("cvt.rna.tf32.f32 %0, %1;" : "=r"(r) : "f"(x)); return r;
}

__device__ __forceinline__ void mma8(float* c,
                                     unsigned a0, unsigned a1, unsigned a2, unsigned a3,
                                     unsigned b0, unsigned b1)
{
    asm volatile("mma.sync.aligned.m16n8k8.row.col.f32.tf32.tf32.f32 "
                 "{%0,%1,%2,%3},{%4,%5,%6,%7},{%8,%9},{%0,%1,%2,%3};"
                 : "+f"(c[0]), "+f"(c[1]), "+f"(c[2]), "+f"(c[3])
                 : "r"(a0), "r"(a1), "r"(a2), "r"(a3), "r"(b0), "r"(b1));
}

// =====================================================================
// Tensor-core tf32 (3xTF32) GEMM, C = A * W^T (+bias)  — unchanged from R8
// =====================================================================
__global__ void __launch_bounds__(256)
tgemm_nt(int M, int N, int K,
         const float* __restrict__ A, long long lda, long long bsA,
         const float* __restrict__ W, long long ldw, long long bsW,
         float* __restrict__ C, long long ldc, long long bsC,
         const float* __restrict__ bias)
{
    __shared__ float sA[2][128 * 20];
    __shared__ float sB[2][128 * 20];

    const int tid = threadIdx.x;
    const int n0 = blockIdx.x * 128;
    const int m0 = blockIdx.y * 128;
    A += (long long)blockIdx.z * bsA;
    W += (long long)blockIdx.z * bsW;
    C += (long long)blockIdx.z * bsC;

    const int w    = tid >> 5;
    const int lane = tid & 31;
    const int lq   = lane >> 2;
    const int lr   = lane & 3;
    const int wm   = (w & 3) * 32;
    const int wn   = (w >> 2) * 64;

    float acc[2][8][4];
#pragma unroll
    for (int mt = 0; mt < 2; mt++)
#pragma unroll
        for (int nt = 0; nt < 8; nt++)
#pragma unroll
            for (int i = 0; i < 4; i++) acc[mt][nt][i] = 0.0f;

    const int nkt = K >> 4;

    auto load_stage = [&](int s, int kt) {
#pragma unroll
        for (int i = 0; i < 2; i++) {
            int idx = i * 256 + tid;
            int row = idx >> 2, c4 = idx & 3;
            cp_async16(&sA[s][row * 20 + c4 * 4],
                       A + (long long)(m0 + row) * lda + kt * 16 + c4 * 4);
            cp_async16(&sB[s][row * 20 + c4 * 4],
                       W + (long long)(n0 + row) * ldw + kt * 16 + c4 * 4);
        }
        asm volatile("cp.async.commit_group;\n");
    };

    load_stage(0, 0);

    for (int kt = 0; kt < nkt; kt++) {
        int cur = kt & 1;
        if (kt + 1 < nkt) {
            load_stage(cur ^ 1, kt + 1);
            asm volatile("cp.async.wait_group 1;\n");
        } else {
            asm volatile("cp.async.wait_group 0;\n");
        }
        __syncthreads();

        const float* pA = sA[cur];
        const float* pB = sB[cur];

#pragma unroll
        for (int kl = 0; kl < 16; kl += 8) {
            unsigned ahi[2][4], alo[2][4];
#pragma unroll
            for (int mt = 0; mt < 2; mt++) {
                int rb = wm + mt * 16 + lq;
                float a0 = pA[rb * 20 + kl + lr];
                float a1 = pA[(rb + 8) * 20 + kl + lr];
                float a2 = pA[rb * 20 + kl + lr + 4];
                float a3 = pA[(rb + 8) * 20 + kl + lr + 4];
                ahi[mt][0] = f2tf(a0); alo[mt][0] = f2tf(a0 - __uint_as_float(ahi[mt][0]));
                ahi[mt][1] = f2tf(a1); alo[mt][1] = f2tf(a1 - __uint_as_float(ahi[mt][1]));
                ahi[mt][2] = f2tf(a2); alo[mt][2] = f2tf(a2 - __uint_as_float(ahi[mt][2]));
                ahi[mt][3] = f2tf(a3); alo[mt][3] = f2tf(a3 - __uint_as_float(ahi[mt][3]));
            }
#pragma unroll
            for (int nt = 0; nt < 8; nt++) {
                int nr = wn + nt * 8 + lq;
                float b0 = pB[nr * 20 + kl + lr];
                float b1 = pB[nr * 20 + kl + lr + 4];
                unsigned bh0 = f2tf(b0), bh1 = f2tf(b1);
                unsigned bl0 = f2tf(b0 - __uint_as_float(bh0));
                unsigned bl1 = f2tf(b1 - __uint_as_float(bh1));
#pragma unroll
                for (int mt = 0; mt < 2; mt++) {
                    mma8(acc[mt][nt], alo[mt][0], alo[mt][1], alo[mt][2], alo[mt][3], bh0, bh1);
                    mma8(acc[mt][nt], ahi[mt][0], ahi[mt][1], ahi[mt][2], ahi[mt][3], bl0, bl1);
                    mma8(acc[mt][nt], ahi[mt][0], ahi[mt][1], ahi[mt][2], ahi[mt][3], bh0, bh1);
                }
            }
        }
        __syncthreads();
    }

#pragma unroll
    for (int mt = 0; mt < 2; mt++) {
#pragma unroll
        for (int nt = 0; nt < 8; nt++) {
            int row = m0 + wm + mt * 16 + lq;
            int col = n0 + wn + nt * 8 + lr * 2;
            float bc0 = bias ? bias[col]     : 0.0f;
            float bc1 = bias ? bias[col + 1] : 0.0f;
            float2 v0 = make_float2(acc[mt][nt][0] + bc0, acc[mt][nt][1] + bc1);
            float2 v1 = make_float2(acc[mt][nt][2] + bc0, acc[mt][nt][3] + bc1);
            *(float2*)&C[(long long)row * ldc + col]       = v0;
            *(float2*)&C[(long long)(row + 8) * ldc + col] = v1;
        }
    }
}

// =====================================================================
// Tensor-core tf32 (3xTF32) GEMM, C = A * B  — unchanged from R8
// =====================================================================
__global__ void __launch_bounds__(256)
tgemm_nn(int M, int N, int K,
         const float* __restrict__ A, long long lda, long long bsA,
         const float* __restrict__ B, long long ldb, long long bsB,
         float* __restrict__ C, long long ldc, long long bsC)
{
    __shared__ float sA[2][128 * 20];
    __shared__ float sB[2][16 * 132];

    const int tid = threadIdx.x;
    const int n0 = blockIdx.x * 128;
    const int m0 = blockIdx.y * 128;
    A += (long long)blockIdx.z * bsA;
    B += (long long)blockIdx.z * bsB;
    C += (long long)blockIdx.z * bsC;

    const int w    = tid >> 5;
    const int lane = tid & 31;
    const int lq   = lane >> 2;
    const int lr   = lane & 3;
    const int wm   = (w & 3) * 32;
    const int wn   = (w >> 2) * 64;

    float acc[2][8][4];
#pragma unroll
    for (int mt = 0; mt < 2; mt++)
#pragma unroll
        for (int nt = 0; nt < 8; nt++)
#pragma unroll
            for (int i = 0; i < 4; i++) acc[mt][nt][i] = 0.0f;

    const int nkt = K >> 4;

    auto load_stage = [&](int s, int kt) {
#pragma unroll
        for (int i = 0; i < 2; i++) {
            int idx = i * 256 + tid;
            int row = idx >> 2, c4 = idx & 3;
            cp_async16(&sA[s][row * 20 + c4 * 4],
                       A + (long long)(m0 + row) * lda + kt * 16 + c4 * 4);
            int kr = idx >> 5, nc = idx & 31;
            cp_async16(&sB[s][kr * 132 + nc * 4],
                       B + (long long)(kt * 16 + kr) * ldb + n0 + nc * 4);
        }
        asm volatile("cp.async.commit_group;\n");
    };

    load_stage(0, 0);

    for (int kt = 0; kt < nkt; kt++) {
        int cur = kt & 1;
        if (kt + 1 < nkt) {
            load_stage(cur ^ 1, kt + 1);
            asm volatile("cp.async.wait_group 1;\n");
        } else {
            asm volatile("cp.async.wait_group 0;\n");
        }
        __syncthreads();

        const float* pA = sA[cur];
        const float* pB = sB[cur];

#pragma unroll
        for (int kl = 0; kl < 16; kl += 8) {
            unsigned ahi[2][4], alo[2][4];
#pragma unroll
            for (int mt = 0; mt < 2; mt++) {
                int rb = wm + mt * 16 + lq;
                float a0 = pA[rb * 20 + kl + lr];
                float a1 = pA[(rb + 8) * 20 + kl + lr];
                float a2 = pA[rb * 20 + kl + lr + 4];
                float a3 = pA[(rb + 8) * 20 + kl + lr + 4];
                ahi[mt][0] = f2tf(a0); alo[mt][0] = f2tf(a0 - __uint_as_float(ahi[mt][0]));
                ahi[mt][1] = f2tf(a1); alo[mt][1] = f2tf(a1 - __uint_as_float(ahi[mt][1]));
                ahi[mt][2] = f2tf(a2); alo[mt][2] = f2tf(a2 - __uint_as_float(ahi[mt][2]));
                ahi[mt][3] = f2tf(a3); alo[mt][3] = f2tf(a3 - __uint_as_float(ahi[mt][3]));
            }
#pragma unroll
            for (int nt = 0; nt < 8; nt++) {
                int nc = wn + nt * 8 + lq;
                float b0 = pB[(kl + lr) * 132 + nc];
                float b1 = pB[(kl + lr + 4) * 132 + nc];
                unsigned bh0 = f2tf(b0), bh1 = f2tf(b1);
                unsigned bl0 = f2tf(b0 - __uint_as_float(bh0));
                unsigned bl1 = f2tf(b1 - __uint_as_float(bh1));
#pragma unroll
                for (int mt = 0; mt < 2; mt++) {
                    mma8(acc[mt][nt], alo[mt][0], alo[mt][1], alo[mt][2], alo[mt][3], bh0, bh1);
                    mma8(acc[mt][nt], ahi[mt][0], ahi[mt][1], ahi[mt][2], ahi[mt][3], bl0, bl1);
                    mma8(acc[mt][nt], ahi[mt][0], ahi[mt][1], ahi[mt][2], ahi[mt][3], bh0, bh1);
                }
            }
        }
        __syncthreads();
    }

#pragma unroll
    for (int mt = 0; mt < 2; mt++) {
#pragma unroll
        for (int nt = 0; nt < 8; nt++) {
            int row = m0 + wm + mt * 16 + lq;
            int col = n0 + wn + nt * 8 + lr * 2;
            *(float2*)&C[(long long)row * ldc + col] =
                make_float2(acc[mt][nt][0], acc[mt][nt][1]);
            *(float2*)&C[(long long)(row + 8) * ldc + col] =
                make_float2(acc[mt][nt][2], acc[mt][nt][3]);
        }
    }
}

// =====================================================================
// Prep: pre-split W_hh into (hi,lo) float2, block-ordered and k-permuted.
//   Block blk owns hidden cols j = 4blk..4blk+3; row cc = jj*3 + g maps to
//   W_hh[g*1024 + 4blk + jj]. k-permutation within each 8-group puts
//   (k, k+4) adjacent so A/B fragments load as one LDS.128.
// =====================================================================
__global__ void prep_whh(const float* __restrict__ W_hh, float2* __restrict__ Wsplit)
{
    long long i = (long long)blockIdx.x * blockDim.x + threadIdx.x;  // 3072*1024
    if (i >= (long long)3072 * 1024) return;
    int r = (int)(i >> 10), k = (int)(i & 1023);
    int blk = r / 12, cc = r % 12;
    int srow = (cc % 3) * 1024 + blk * 4 + cc / 3;
    float x = W_hh[(long long)srow * 1024 + k];
    float hi = __uint_as_float(f2tf(x));
    float lo = __uint_as_float(f2tf(x - hi));
    int kp = (k & ~7) | ((k & 3) << 1) | ((k >> 2) & 1);
    Wsplit[(long long)r * 1024 + kp] = make_float2(hi, lo);
}

// =====================================================================
// Persistent GRU recurrence — tensor-core (3xTF32) version.
//   256 blocks x 256 threads, 2/SM. Per step: gh_slice[64 x 12] =
//   h[64 x 1024] @ Wslice^T. W pre-split in global (L2-hot); h staged f32
//   via cp.async in 64-k chunks, cooperatively split to tf32 (hi,lo) in
//   smem (k-permuted). 8 warps = (khalf, nt, mt-pair); partial D frags
//   exchanged via smem; gates fused; grid barrier per step.
//   W rows 12..15 of staging are zero (N padded 12->16).
// =====================================================================
extern __shared__ float rsm[];
// float offsets within rsm:
//   sW      : [2][16*66] float2  -> floats [0, 4224)
//   sHstage : [2][64*64] float   -> floats [4224, 12416)
//   sHsplit : [64*66] float2     -> floats [12416, 20864)
//   sGH     : [2][64*16] float   -> floats [20864, 22912)
#define RS_W      0
#define RS_HSTAGE 4224
#define RS_HSPLIT 12416
#define RS_GH     20864
#define RSM_BYTES (22912 * 4)

__global__ void __launch_bounds__(RTHREADS, 2)
gru_persistent(const float* __restrict__ gi,
               const float2* __restrict__ Wsplit,
               const float* __restrict__ b_hh,
               const float* __restrict__ h_init,
               const int* __restrict__ length,
               float* __restrict__ h2,          // [2][B*H]
               float* __restrict__ out_hs,      // [S][B][2H]
               float* __restrict__ out_hlast,   // [B][H]
               unsigned* __restrict__ bar)
{
    const int tid  = threadIdx.x;
    const int w    = tid >> 5;
    const int lane = tid & 31;
    const int lq   = lane >> 2;
    const int lr   = lane & 3;
    const int khalf = w >> 2;        // 0..1
    const int nt    = (w >> 1) & 1;  // 0..1
    const int mtg   = w & 1;         // 0..1 -> m rows [mtg*32, mtg*32+32)

    float2* sW   = (float2*)(rsm + RS_W);        // [2][16*66]
    float*  sHs  = rsm + RS_HSTAGE;              // [2][64*64]
    float2* sHsp = (float2*)(rsm + RS_HSPLIT);   // [64*66]
    float*  sGH  = rsm + RS_GH;                  // [2][64*16]

    // gate-thread identity: (b, jj)
    const int gb = tid >> 2;
    const int gjj = tid & 3;
    const int gj = blockIdx.x * 4 + gjj;
    const float bh_r = b_hh[gj];
    const float bh_z = b_hh[1024 + gj];
    const float bh_n = b_hh[2048 + gj];
    const int   len_b = length[gb];

    // zero padded W rows (12..15) in both staging buffers (never overwritten)
    for (int v = tid; v < 2 * 4 * 66; v += RTHREADS) {
        int st = v / 264, rem = v % 264;
        sW[st * 1056 + (12 + rem / 66) * 66 + (rem % 66)] = make_float2(0.0f, 0.0f);
    }

    // init h buffer 0 (grid covers exactly 64*1024 elements)
    {
        int v = blockIdx.x * RTHREADS + tid;
        h2[v] = h_init[v & (HDIM - 1)];
    }

    unsigned phase = 1;
    {
        __threadfence(); __syncthreads();
        if (tid == 0) {
            atomicAdd(bar, 1u);
            while (*((volatile unsigned*)bar) < phase * RBLOCKS) { __nanosleep(32); }
        }
        __syncthreads();
    }

    const float2* Wblk = Wsplit + (long long)blockIdx.x * 12 * 1024;

    auto stage = [&](int st, int c, const float* hcur) {
        // W chunk: 12 rows x 32 float2-pairs (16B each) = 384 ops
#pragma unroll
        for (int i = 0; i < 2; i++) {
            int id = i * 256 + tid;
            if (id < 384) {
                int row = id >> 5;
                int kp  = (id & 31) * 2;
                cp_async16(&sW[st * 1056 + row * 66 + kp],
                           Wblk + (long long)row * 1024 + c * 64 + kp);
            }
        }
        // H chunk: 64 rows x 16 float4 = 1024 ops
#pragma unroll
        for (int i = 0; i < 4; i++) {
            int id = i * 256 + tid;
            int row = id >> 4;
            int k4  = (id & 15) * 4;
            cp_async16(&sHs[st * 4096 + row * 64 + k4],
                       hcur + row * 1024 + c * 64 + k4);
        }
        asm volatile("cp.async.commit_group;\n");
    };

    for (int s = 0; s < SEQ; s++) {
        const float* hcur = h2 + (s & 1) * (BATCH * HDIM);
        float*       hnxt = h2 + ((s + 1) & 1) * (BATCH * HDIM);

        // prefetch gi + h_old (consumed in gates)
        const float* gis = gi + (long long)s * (BATCH * 3 * HDIM) + gb * 3 * HDIM;
        float gi_r  = __ldg(&gis[gj]);
        float gi_z  = __ldg(&gis[1024 + gj]);
        float gi_n  = __ldg(&gis[2048 + gj]);
        float h_old = __ldcg(&hcur[gb * 1024 + gj]);

        float acc[2][4];
#pragma unroll
        for (int p = 0; p < 2; p++)
#pragma unroll
            for (int i = 0; i < 4; i++) acc[p][i] = 0.0f;

        stage(0, 0, hcur);

        for (int c = 0; c < 16; c++) {
            int cur = c & 1;
            if (c + 1 < 16) {
                stage(cur ^ 1, c + 1, hcur);
                asm volatile("cp.async.wait_group 1;\n");
            } else {
                asm volatile("cp.async.wait_group 0;\n");
            }
            __syncthreads();   // staged data ready; prev mma done reading sHsp

            // cooperative tf32 split of h chunk (k-permuted)
            const float* src = sHs + cur * 4096;
#pragma unroll
            for (int t = 0; t < 16; t++) {
                int id = t * 256 + tid;
                int row = id >> 6, k = id & 63;
                float x = src[row * 64 + k];
                float hi = __uint_as_float(f2tf(x));
                float lo = __uint_as_float(f2tf(x - hi));
                int pc = (k & ~7) | ((k & 3) << 1) | ((k >> 2) & 1);
                sHsp[row * 66 + pc] = make_float2(hi, lo);
            }
            __syncthreads();   // split ready

            // mma: this warp covers khalf (32 k), nt (8 cols), mtg (32 rows)
            const float2* pW = sW + cur * 1056;
            const int nr = nt * 8 + lq;
#pragma unroll
            for (int ks = 0; ks < 4; ks++) {
                int kl = khalf * 32 + ks * 8;
                float4 bv = *(const float4*)&pW[nr * 66 + kl + lr * 2];
                unsigned bh0 = __float_as_uint(bv.x), bl0 = __float_as_uint(bv.y);
                unsigned bh1 = __float_as_uint(bv.z), bl1 = __float_as_uint(bv.w);
#pragma unroll
                for (int p = 0; p < 2; p++) {
                    int row = mtg * 32 + p * 16 + lq;
                    float4 av0 = *(const float4*)&sHsp[row * 66 + kl + lr * 2];
                    float4 av1 = *(const float4*)&sHsp[(row + 8) * 66 + kl + lr * 2];
                    mma8(acc[p], __float_as_uint(av0.y), __float_as_uint(av1.y),
                                 __float_as_uint(av0.w), __float_as_uint(av1.w), bh0, bh1);
                    mma8(acc[p], __float_as_uint(av0.x), __float_as_uint(av1.x),
                                 __float_as_uint(av0.z), __float_as_uint(av1.z), bl0, bl1);
                    mma8(acc[p], __float_as_uint(av0.x), __float_as_uint(av1.x),
                                 __float_as_uint(av0.z), __float_as_uint(av1.z), bh0, bh1);
                }
            }
        }
        __syncthreads();   // all mma done before sGH writes (sGH read last step by gates)

        // exchange D fragments via smem
        {
            int col = nt * 8 + lr * 2;
#pragma unroll
            for (int p = 0; p < 2; p++) {
                int row = mtg * 32 + p * 16 + lq;
                *(float2*)&sGH[khalf * 1024 + row * 16 + col] =
                    make_float2(acc[p][0], acc[p][1]);
                *(float2*)&sGH[khalf * 1024 + (row + 8) * 16 + col] =
                    make_float2(acc[p][2], acc[p][3]);
            }
        }
        __syncthreads();

        // fused gates: thread handles (gb, gjj)
        {
            int c_r = gjj * 3 + 0, c_z = gjj * 3 + 1, c_n = gjj * 3 + 2;
            float ghr = sGH[gb * 16 + c_r] + sGH[1024 + gb * 16 + c_r] + bh_r;
            float ghz = sGH[gb * 16 + c_z] + sGH[1024 + gb * 16 + c_z] + bh_z;
            float ghn = sGH[gb * 16 + c_n] + sGH[1024 + gb * 16 + c_n] + bh_n;
            float r = 1.0f / (1.0f + expf(-(gi_r + ghr)));
            float z = 1.0f / (1.0f + expf(-(gi_z + ghz)));
            float n = tanhf(gi_n + r * ghn);
            float keep = (s < len_b) ? 1.0f : 0.0f;
            float hnew = (n + z * (h_old - n)) * keep;

            hnxt[gb * 1024 + gj] = hnew;
            out_hs[(long long)s * (BATCH * 2 * HDIM) + gb * (2 * HDIM) + gj] = hnew;
            if (s == SEQ - 1) out_hlast[gb * 1024 + gj] = hnew;
        }

        // end-of-step barrier
        phase++;
        __threadfence(); __syncthreads();
        if (tid == 0) {
            atomicAdd(bar, 1u);
            while (*((volatile unsigned*)bar) < phase * RBLOCKS) { __nanosleep(32); }
        }
        __syncthreads();
    }
}

// =====================================================================
// Softmax — unchanged from R8
// =====================================================================
__global__ void attn_softmax_kernel(const float* __restrict__ scores,   // [b][s][l]
                                    const int* __restrict__ post_length,
                                    float* __restrict__ attn_scratch,   // [b][s][l]
                                    float* __restrict__ out_attn)       // [s][l][b]
{
    int s = blockIdx.x;
    int b = blockIdx.y;
    int l = threadIdx.x;

    float sc = scores[((long long)b * SEQ + s) * PLEN + l];
    if (l >= post_length[b]) sc = -1000000000.0f;

    __shared__ float red[PLEN];
    red[l] = sc;
    __syncthreads();
#pragma unroll
    for (int o = PLEN / 2; o > 0; o >>= 1) {
        if (l < o) red[l] = fmaxf(red[l], red[l + o]);
        __syncthreads();
    }
    float mx = red[0];
    __syncthreads();

    float e = expf(sc - mx);
    red[l] = e;
    __syncthreads();
#pragma unroll
    for (int o = PLEN / 2; o > 0; o >>= 1) {
        if (l < o) red[l] += red[l + o];
        __syncthreads();
    }
    float a = e / red[0];

    attn_scratch[((long long)b * SEQ + s) * PLEN + l] = a;
    out_attn[(long long)s * (PLEN * BATCH) + l * BATCH + b] = a;
}

// =====================================================================
// launch
// =====================================================================
extern "C" void kernel_launch(void* const* d_in, const int* in_sizes, int n_in,
                              void* d_out, int out_size)
{
    (void)in_sizes; (void)n_in; (void)out_size;

    const float* incoming = (const float*)d_in[0];
    const float* post     = (const float*)d_in[1];
    const float* h_init   = (const float*)d_in[2];
    const float* W_ih     = (const float*)d_in[3];
    const float* W_hh     = (const float*)d_in[4];
    const float* b_ih     = (const float*)d_in[5];
    const float* b_hh     = (const float*)d_in[6];
    const float* Wq       = (const float*)d_in[7];
    const float* bq       = (const float*)d_in[8];
    const int*   length      = (const int*)d_in[9];
    const int*   post_length = (const int*)d_in[10];

    float* out       = (float*)d_out;
    float* out_hlast = out;                                   // [B, H]
    float* out_hs    = out + BATCH * HDIM;                    // [S, B, 2H]
    float* out_attn  = out_hs + (long long)SEQ * BATCH * 2 * HDIM;  // [S, PL, B]

    float *gi, *h2, *query, *scores, *attn;
    float2* Whh2;
    unsigned* bar;
    cudaGetSymbolAddress((void**)&gi,     g_gi);
    cudaGetSymbolAddress((void**)&h2,     g_h2);
    cudaGetSymbolAddress((void**)&query,  g_query);
    cudaGetSymbolAddress((void**)&scores, g_scores);
    cudaGetSymbolAddress((void**)&attn,   g_attn);
    cudaGetSymbolAddress((void**)&Whh2,   g_Whh2);
    cudaGetSymbolAddress((void**)&bar,    g_bar);

    cudaFuncSetAttribute(gru_persistent,
                         cudaFuncAttributeMaxDynamicSharedMemorySize, RSM_BYTES);

    const int MALL = SEQ * BATCH;   // 16384

    // Prep: pre-split W_hh (runs every launch; ~36MB traffic)
    prep_whh<<<(3072 * 1024 + 255) / 256, 256>>>(W_hh, Whh2);

    // Phase A: gi = incoming @ W_ih^T + b_ih  [16384, 3072] k=1024
    tgemm_nt<<<dim3(3 * HDIM / 128, MALL / 128), 256>>>(
        MALL, 3 * HDIM, IDIM,
        incoming, IDIM, 0,
        W_ih, IDIM, 0,
        gi, 3 * HDIM, 0,
        b_ih);

    // Phase B: persistent tensor-core GRU recurrence
    cudaMemsetAsync(bar, 0, sizeof(unsigned));
    gru_persistent<<<RBLOCKS, RTHREADS, RSM_BYTES>>>(
        gi, Whh2, b_hh, h_init, length, h2, out_hs, out_hlast, bar);

    // Phase C: query = h_all @ Wq^T + bq (h read from hs region, stride 2H)
    tgemm_nt<<<dim3(PDIM / 128, MALL / 128), 256>>>(
        MALL, PDIM, HDIM,
        out_hs, 2 * HDIM, 0,
        Wq, HDIM, 0,
        query, PDIM, 0,
        bq);

    // Phase D1: scores_b = Q_b @ post_b^T (batched over b)
    tgemm_nt<<<dim3(PLEN / 128, SEQ / 128, BATCH), 256>>>(
        SEQ, PLEN, PDIM,
        query, (long long)BATCH * PDIM, PDIM,
        post, (long long)BATCH * PDIM, PDIM,
        scores, PLEN, (long long)SEQ * PLEN,
        (const float*)nullptr);

    // Phase D2: masked softmax over l
    attn_softmax_kernel<<<dim3(SEQ, BATCH), PLEN>>>(scores, post_length, attn, out_attn);

    // Phase D3: context_b = attn_b @ post_b
    tgemm_nn<<<dim3(PDIM / 128, SEQ / 128, BATCH), 256>>>(
        SEQ, PDIM, PLEN,
        attn, PLEN, (long long)SEQ * PLEN,
        post, (long long)BATCH * PDIM, PDIM,
        out_hs + HDIM, (long long)BATCH * 2 * HDIM, 2 * HDIM);
}

// round 12
// speedup vs baseline: 2.2549x; 2.2549x over previous
#include <cuda_runtime.h>
#include <math.h>

// Problem dims
#define SEQ   256
#define BATCH 64
#define IDIM  1024
#define HDIM  1024
#define PLEN  256
#define PDIM  1024

#define RBLOCKS  256
#define RTHREADS 256

// -------- device scratch (no runtime allocation allowed) --------
__device__ __align__(16) float g_gi[SEQ * BATCH * 3 * HDIM];   // precomputed input gates
__device__ __align__(16) float g_h2[2 * BATCH * HDIM];         // double-buffered hidden state
__device__ float g_query[SEQ * BATCH * PDIM];
__device__ float g_scores[BATCH * SEQ * PLEN];
__device__ float g_attn[BATCH * SEQ * PLEN];
__device__ __align__(16) float2 g_Wih2[3 * HDIM * IDIM];       // pre-split W_ih (hi,lo)
__device__ __align__(16) float2 g_Wq2[PDIM * HDIM];            // pre-split Wq (hi,lo)
__device__ unsigned g_bar;                                     // grid barrier counter

extern __shared__ float rsm[];

// =====================================================================
// helpers
// =====================================================================
__device__ __forceinline__ void cp_async16(void* smem_dst, const void* gmem_src)
{
    unsigned ds = (unsigned)__cvta_generic_to_shared(smem_dst);
    asm volatile("cp.async.cg.shared.global [%0], [%1], 16;\n" :: "r"(ds), "l"(gmem_src));
}

__device__ __forceinline__ unsigned f2tf(float x)
{
    unsigned r; asm("cvt.rna.tf32.f32 %0, %1;" : "=r"(r) : "f"(x)); return r;
}

__device__ __forceinline__ void mma8(float* c,
                                     unsigned a0, unsigned a1, unsigned a2, unsigned a3,
                                     unsigned b0, unsigned b1)
{
    asm volatile("mma.sync.aligned.m16n8k8.row.col.f32.tf32.tf32.f32 "
                 "{%0,%1,%2,%3},{%4,%5,%6,%7},{%8,%9},{%0,%1,%2,%3};"
                 : "+f"(c[0]), "+f"(c[1]), "+f"(c[2]), "+f"(c[3])
                 : "r"(a0), "r"(a1), "r"(a2), "r"(a3), "r"(b0), "r"(b1));
}

// =====================================================================
// Weight split pre-pass: dst[i] = (hi, lo) tf32 split of src[i]
// =====================================================================
__global__ void split_w(const float* __restrict__ src, float2* __restrict__ dst, int n)
{
    int i = blockIdx.x * blockDim.x + threadIdx.x;
    if (i < n) {
        float x = src[i];
        float hi = __uint_as_float(f2tf(x));
        float lo = __uint_as_float(f2tf(x - hi));
        dst[i] = make_float2(hi, lo);
    }
}

// =====================================================================
// Tensor-core tf32 (3xTF32) GEMM, C = A * W^T (+bias), W PRE-SPLIT.
//   A [M,K] f32 rows stride lda (split in-register);
//   W [N,K] float2 (hi,lo) rows stride ldw -> B fragments are pure loads.
//   128x128x16 tiles, 8 warps (4M x 2N), 2-stage cp.async pipeline.
//   Dynamic smem: sA f32 [2][128*20], sB float2 [2][128*18].
// =====================================================================
#define WS_SMEM (2 * 2560 * 4 + 2 * 2304 * 8)   // 57344 bytes

__global__ void __launch_bounds__(256)
tgemm_nt_ws(int M, int N, int K,
            const float* __restrict__ A, long long lda,
            const float2* __restrict__ W, long long ldw,
            float* __restrict__ C, long long ldc,
            const float* __restrict__ bias)
{
    float*  sA = rsm;                         // [2][128*20] f32
    float2* sB = (float2*)(rsm + 2 * 2560);   // [2][128*18] float2

    const int tid = threadIdx.x;
    const int n0 = blockIdx.x * 128;
    const int m0 = blockIdx.y * 128;

    const int w    = tid >> 5;
    const int lane = tid & 31;
    const int lq   = lane >> 2;
    const int lr   = lane & 3;
    const int wm   = (w & 3) * 32;
    const int wn   = (w >> 2) * 64;

    float acc[2][8][4];
#pragma unroll
    for (int mt = 0; mt < 2; mt++)
#pragma unroll
        for (int nt = 0; nt < 8; nt++)
#pragma unroll
            for (int i = 0; i < 4; i++) acc[mt][nt][i] = 0.0f;

    const int nkt = K >> 4;

    auto load_stage = [&](int st, int kt) {
#pragma unroll
        for (int i = 0; i < 2; i++) {
            int idx = i * 256 + tid;
            int row = idx >> 2, c4 = idx & 3;
            cp_async16(&sA[st * 2560 + row * 20 + c4 * 4],
                       A + (long long)(m0 + row) * lda + kt * 16 + c4 * 4);
        }
#pragma unroll
        for (int i = 0; i < 4; i++) {
            int idx = i * 256 + tid;
            int row = idx >> 3, sg = idx & 7;
            cp_async16(&sB[st * 2304 + row * 18 + sg * 2],
                       W + (long long)(n0 + row) * ldw + kt * 16 + sg * 2);
        }
        asm volatile("cp.async.commit_group;\n");
    };

    load_stage(0, 0);

    for (int kt = 0; kt < nkt; kt++) {
        int cur = kt & 1;
        if (kt + 1 < nkt) {
            load_stage(cur ^ 1, kt + 1);
            asm volatile("cp.async.wait_group 1;\n");
        } else {
            asm volatile("cp.async.wait_group 0;\n");
        }
        __syncthreads();

        const float*  pA = sA + cur * 2560;
        const float2* pB = sB + cur * 2304;

#pragma unroll
        for (int kl = 0; kl < 16; kl += 8) {
            unsigned ahi[2][4], alo[2][4];
#pragma unroll
            for (int mt = 0; mt < 2; mt++) {
                int rb = wm + mt * 16 + lq;
                float a0 = pA[rb * 20 + kl + lr];
                float a1 = pA[(rb + 8) * 20 + kl + lr];
                float a2 = pA[rb * 20 + kl + lr + 4];
                float a3 = pA[(rb + 8) * 20 + kl + lr + 4];
                ahi[mt][0] = f2tf(a0); alo[mt][0] = f2tf(a0 - __uint_as_float(ahi[mt][0]));
                ahi[mt][1] = f2tf(a1); alo[mt][1] = f2tf(a1 - __uint_as_float(ahi[mt][1]));
                ahi[mt][2] = f2tf(a2); alo[mt][2] = f2tf(a2 - __uint_as_float(ahi[mt][2]));
                ahi[mt][3] = f2tf(a3); alo[mt][3] = f2tf(a3 - __uint_as_float(ahi[mt][3]));
            }
#pragma unroll
            for (int nt = 0; nt < 8; nt++) {
                int nr = wn + nt * 8 + lq;
                float2 b0 = pB[nr * 18 + kl + lr];
                float2 b1 = pB[nr * 18 + kl + lr + 4];
                unsigned bh0 = __float_as_uint(b0.x), bl0 = __float_as_uint(b0.y);
                unsigned bh1 = __float_as_uint(b1.x), bl1 = __float_as_uint(b1.y);
#pragma unroll
                for (int mt = 0; mt < 2; mt++) {
                    mma8(acc[mt][nt], alo[mt][0], alo[mt][1], alo[mt][2], alo[mt][3], bh0, bh1);
                    mma8(acc[mt][nt], ahi[mt][0], ahi[mt][1], ahi[mt][2], ahi[mt][3], bl0, bl1);
                    mma8(acc[mt][nt], ahi[mt][0], ahi[mt][1], ahi[mt][2], ahi[mt][3], bh0, bh1);
                }
            }
        }
        __syncthreads();
    }

#pragma unroll
    for (int mt = 0; mt < 2; mt++) {
#pragma unroll
        for (int nt = 0; nt < 8; nt++) {
            int row = m0 + wm + mt * 16 + lq;
            int col = n0 + wn + nt * 8 + lr * 2;
            float bc0 = bias ? bias[col]     : 0.0f;
            float bc1 = bias ? bias[col + 1] : 0.0f;
            float2 v0 = make_float2(acc[mt][nt][0] + bc0, acc[mt][nt][1] + bc1);
            float2 v1 = make_float2(acc[mt][nt][2] + bc0, acc[mt][nt][3] + bc1);
            *(float2*)&C[(long long)row * ldc + col]       = v0;
            *(float2*)&C[(long long)(row + 8) * ldc + col] = v1;
        }
    }
}

// =====================================================================
// Tensor-core tf32 (3xTF32) GEMM, C = A * W^T (+bias) — R8 version (f32 W)
// =====================================================================
__global__ void __launch_bounds__(256)
tgemm_nt(int M, int N, int K,
         const float* __restrict__ A, long long lda, long long bsA,
         const float* __restrict__ W, long long ldw, long long bsW,
         float* __restrict__ C, long long ldc, long long bsC,
         const float* __restrict__ bias)
{
    __shared__ float sA[2][128 * 20];
    __shared__ float sB[2][128 * 20];

    const int tid = threadIdx.x;
    const int n0 = blockIdx.x * 128;
    const int m0 = blockIdx.y * 128;
    A += (long long)blockIdx.z * bsA;
    W += (long long)blockIdx.z * bsW;
    C += (long long)blockIdx.z * bsC;

    const int w    = tid >> 5;
    const int lane = tid & 31;
    const int lq   = lane >> 2;
    const int lr   = lane & 3;
    const int wm   = (w & 3) * 32;
    const int wn   = (w >> 2) * 64;

    float acc[2][8][4];
#pragma unroll
    for (int mt = 0; mt < 2; mt++)
#pragma unroll
        for (int nt = 0; nt < 8; nt++)
#pragma unroll
            for (int i = 0; i < 4; i++) acc[mt][nt][i] = 0.0f;

    const int nkt = K >> 4;

    auto load_stage = [&](int s, int kt) {
#pragma unroll
        for (int i = 0; i < 2; i++) {
            int idx = i * 256 + tid;
            int row = idx >> 2, c4 = idx & 3;
            cp_async16(&sA[s][row * 20 + c4 * 4],
                       A + (long long)(m0 + row) * lda + kt * 16 + c4 * 4);
            cp_async16(&sB[s][row * 20 + c4 * 4],
                       W + (long long)(n0 + row) * ldw + kt * 16 + c4 * 4);
        }
        asm volatile("cp.async.commit_group;\n");
    };

    load_stage(0, 0);

    for (int kt = 0; kt < nkt; kt++) {
        int cur = kt & 1;
        if (kt + 1 < nkt) {
            load_stage(cur ^ 1, kt + 1);
            asm volatile("cp.async.wait_group 1;\n");
        } else {
            asm volatile("cp.async.wait_group 0;\n");
        }
        __syncthreads();

        const float* pA = sA[cur];
        const float* pB = sB[cur];

#pragma unroll
        for (int kl = 0; kl < 16; kl += 8) {
            unsigned ahi[2][4], alo[2][4];
#pragma unroll
            for (int mt = 0; mt < 2; mt++) {
                int rb = wm + mt * 16 + lq;
                float a0 = pA[rb * 20 + kl + lr];
                float a1 = pA[(rb + 8) * 20 + kl + lr];
                float a2 = pA[rb * 20 + kl + lr + 4];
                float a3 = pA[(rb + 8) * 20 + kl + lr + 4];
                ahi[mt][0] = f2tf(a0); alo[mt][0] = f2tf(a0 - __uint_as_float(ahi[mt][0]));
                ahi[mt][1] = f2tf(a1); alo[mt][1] = f2tf(a1 - __uint_as_float(ahi[mt][1]));
                ahi[mt][2] = f2tf(a2); alo[mt][2] = f2tf(a2 - __uint_as_float(ahi[mt][2]));
                ahi[mt][3] = f2tf(a3); alo[mt][3] = f2tf(a3 - __uint_as_float(ahi[mt][3]));
            }
#pragma unroll
            for (int nt = 0; nt < 8; nt++) {
                int nr = wn + nt * 8 + lq;
                float b0 = pB[nr * 20 + kl + lr];
                float b1 = pB[nr * 20 + kl + lr + 4];
                unsigned bh0 = f2tf(b0), bh1 = f2tf(b1);
                unsigned bl0 = f2tf(b0 - __uint_as_float(bh0));
                unsigned bl1 = f2tf(b1 - __uint_as_float(bh1));
#pragma unroll
                for (int mt = 0; mt < 2; mt++) {
                    mma8(acc[mt][nt], alo[mt][0], alo[mt][1], alo[mt][2], alo[mt][3], bh0, bh1);
                    mma8(acc[mt][nt], ahi[mt][0], ahi[mt][1], ahi[mt][2], ahi[mt][3], bl0, bl1);
                    mma8(acc[mt][nt], ahi[mt][0], ahi[mt][1], ahi[mt][2], ahi[mt][3], bh0, bh1);
                }
            }
        }
        __syncthreads();
    }

#pragma unroll
    for (int mt = 0; mt < 2; mt++) {
#pragma unroll
        for (int nt = 0; nt < 8; nt++) {
            int row = m0 + wm + mt * 16 + lq;
            int col = n0 + wn + nt * 8 + lr * 2;
            float bc0 = bias ? bias[col]     : 0.0f;
            float bc1 = bias ? bias[col + 1] : 0.0f;
            float2 v0 = make_float2(acc[mt][nt][0] + bc0, acc[mt][nt][1] + bc1);
            float2 v1 = make_float2(acc[mt][nt][2] + bc0, acc[mt][nt][3] + bc1);
            *(float2*)&C[(long long)row * ldc + col]       = v0;
            *(float2*)&C[(long long)(row + 8) * ldc + col] = v1;
        }
    }
}

// =====================================================================
// Tensor-core tf32 (3xTF32) GEMM, C = A * B — R8 version
// =====================================================================
__global__ void __launch_bounds__(256)
tgemm_nn(int M, int N, int K,
         const float* __restrict__ A, long long lda, long long bsA,
         const float* __restrict__ B, long long ldb, long long bsB,
         float* __restrict__ C, long long ldc, long long bsC)
{
    __shared__ float sA[2][128 * 20];
    __shared__ float sB[2][16 * 132];

    const int tid = threadIdx.x;
    const int n0 = blockIdx.x * 128;
    const int m0 = blockIdx.y * 128;
    A += (long long)blockIdx.z * bsA;
    B += (long long)blockIdx.z * bsB;
    C += (long long)blockIdx.z * bsC;

    const int w    = tid >> 5;
    const int lane = tid & 31;
    const int lq   = lane >> 2;
    const int lr   = lane & 3;
    const int wm   = (w & 3) * 32;
    const int wn   = (w >> 2) * 64;

    float acc[2][8][4];
#pragma unroll
    for (int mt = 0; mt < 2; mt++)
#pragma unroll
        for (int nt = 0; nt < 8; nt++)
#pragma unroll
            for (int i = 0; i < 4; i++) acc[mt][nt][i] = 0.0f;

    const int nkt = K >> 4;

    auto load_stage = [&](int s, int kt) {
#pragma unroll
        for (int i = 0; i < 2; i++) {
            int idx = i * 256 + tid;
            int row = idx >> 2, c4 = idx & 3;
            cp_async16(&sA[s][row * 20 + c4 * 4],
                       A + (long long)(m0 + row) * lda + kt * 16 + c4 * 4);
            int kr = idx >> 5, nc = idx & 31;
            cp_async16(&sB[s][kr * 132 + nc * 4],
                       B + (long long)(kt * 16 + kr) * ldb + n0 + nc * 4);
        }
        asm volatile("cp.async.commit_group;\n");
    };

    load_stage(0, 0);

    for (int kt = 0; kt < nkt; kt++) {
        int cur = kt & 1;
        if (kt + 1 < nkt) {
            load_stage(cur ^ 1, kt + 1);
            asm volatile("cp.async.wait_group 1;\n");
        } else {
            asm volatile("cp.async.wait_group 0;\n");
        }
        __syncthreads();

        const float* pA = sA[cur];
        const float* pB = sB[cur];

#pragma unroll
        for (int kl = 0; kl < 16; kl += 8) {
            unsigned ahi[2][4], alo[2][4];
#pragma unroll
            for (int mt = 0; mt < 2; mt++) {
                int rb = wm + mt * 16 + lq;
                float a0 = pA[rb * 20 + kl + lr];
                float a1 = pA[(rb + 8) * 20 + kl + lr];
                float a2 = pA[rb * 20 + kl + lr + 4];
                float a3 = pA[(rb + 8) * 20 + kl + lr + 4];
                ahi[mt][0] = f2tf(a0); alo[mt][0] = f2tf(a0 - __uint_as_float(ahi[mt][0]));
                ahi[mt][1] = f2tf(a1); alo[mt][1] = f2tf(a1 - __uint_as_float(ahi[mt][1]));
                ahi[mt][2] = f2tf(a2); alo[mt][2] = f2tf(a2 - __uint_as_float(ahi[mt][2]));
                ahi[mt][3] = f2tf(a3); alo[mt][3] = f2tf(a3 - __uint_as_float(ahi[mt][3]));
            }
#pragma unroll
            for (int nt = 0; nt < 8; nt++) {
                int nc = wn + nt * 8 + lq;
                float b0 = pB[(kl + lr) * 132 + nc];
                float b1 = pB[(kl + lr + 4) * 132 + nc];
                unsigned bh0 = f2tf(b0), bh1 = f2tf(b1);
                unsigned bl0 = f2tf(b0 - __uint_as_float(bh0));
                unsigned bl1 = f2tf(b1 - __uint_as_float(bh1));
#pragma unroll
                for (int mt = 0; mt < 2; mt++) {
                    mma8(acc[mt][nt], alo[mt][0], alo[mt][1], alo[mt][2], alo[mt][3], bh0, bh1);
                    mma8(acc[mt][nt], ahi[mt][0], ahi[mt][1], ahi[mt][2], ahi[mt][3], bl0, bl1);
                    mma8(acc[mt][nt], ahi[mt][0], ahi[mt][1], ahi[mt][2], ahi[mt][3], bh0, bh1);
                }
            }
        }
        __syncthreads();
    }

#pragma unroll
    for (int mt = 0; mt < 2; mt++) {
#pragma unroll
        for (int nt = 0; nt < 8; nt++) {
            int row = m0 + wm + mt * 16 + lq;
            int col = n0 + wn + nt * 8 + lr * 2;
            *(float2*)&C[(long long)row * ldc + col] =
                make_float2(acc[mt][nt][0], acc[mt][nt][1]);
            *(float2*)&C[(long long)(row + 8) * ldc + col] =
                make_float2(acc[mt][nt][2], acc[mt][nt][3]);
        }
    }
}

// =====================================================================
// Persistent GRU recurrence — R6/R8 scalar FFMA version (proven fastest)
// =====================================================================
__global__ void __launch_bounds__(RTHREADS, 2)
gru_persistent(const float* __restrict__ gi,
               const float* __restrict__ W_hh,
               const float* __restrict__ b_hh,
               const float* __restrict__ h_init,
               const int* __restrict__ length,
               float* __restrict__ h2,          // [2][B*H]
               float* __restrict__ out_hs,      // [S][B][2H]
               float* __restrict__ out_hlast,   // [B][H]
               unsigned* __restrict__ bar)
{
    const int tid = threadIdx.x;
    const int bg  = tid >> 4;
    const int ks  = tid & 15;
    const int j0  = blockIdx.x * 4;
    const int b   = bg * 4 + (ks >> 2);
    const int j   = j0 + (ks & 3);

    float* Ws  = rsm;
    float* hb0 = rsm + 12 * 1024;
    float* hb1 = hb0 + 64 * 64;

    for (int v = tid; v < 12 * 256; v += RTHREADS) {
        int cc = v >> 8;
        int cq = v & 255;
        int row = (cc % 3) * 1024 + j0 + (cc / 3);
        ((float4*)Ws)[cc * 256 + cq] = ((const float4*)W_hh)[row * 256 + cq];
    }

    const float bh_r = b_hh[j];
    const float bh_z = b_hh[1024 + j];
    const float bh_n = b_hh[2048 + j];
    const int   len_b = length[b];

    {
        int v = blockIdx.x * RTHREADS + tid;
        h2[v] = h_init[v & (HDIM - 1)];
    }

    unsigned phase = 1;
    {
        __threadfence(); __syncthreads();
        if (tid == 0) {
            atomicAdd(bar, 1u);
            while (*((volatile unsigned*)bar) < phase * RBLOCKS) { __nanosleep(32); }
        }
        __syncthreads();
    }

    for (int s = 0; s < SEQ; s++) {
        const float* hcur = h2 + (s & 1) * (BATCH * HDIM);
        float*       hnxt = h2 + ((s + 1) & 1) * (BATCH * HDIM);
        const float4* hc4 = (const float4*)hcur;

        const float* gis = gi + (long long)s * (BATCH * 3 * HDIM) + b * 3 * HDIM;
        float gi_r  = __ldg(&gis[j]);
        float gi_z  = __ldg(&gis[1024 + j]);
        float gi_n  = __ldg(&gis[2048 + j]);
        float h_old = __ldcg(&hcur[b * 1024 + j]);

        float acc[4][12];
#pragma unroll
        for (int i = 0; i < 4; i++)
#pragma unroll
            for (int cc = 0; cc < 12; cc++) acc[i][cc] = 0.0f;

        {
            float4* dst = (float4*)hb0;
#pragma unroll
            for (int i = 0; i < 4; i++) {
                int idx = i * 256 + tid;
                int bb = idx >> 4, kq = idx & 15;
                cp_async16(&dst[bb * 16 + kq], &hc4[bb * 256 + kq]);
            }
            asm volatile("cp.async.commit_group;\n");
        }

        for (int c = 0; c < 16; c++) {
            const float* cur = (c & 1) ? hb1 : hb0;
            float*       nxt = (c & 1) ? hb0 : hb1;
            if (c + 1 < 16) {
                float4* dst = (float4*)nxt;
#pragma unroll
                for (int i = 0; i < 4; i++) {
                    int idx = i * 256 + tid;
                    int bb = idx >> 4, kq = idx & 15;
                    cp_async16(&dst[bb * 16 + kq], &hc4[bb * 256 + (c + 1) * 16 + kq]);
                }
                asm volatile("cp.async.commit_group;\n");
                asm volatile("cp.async.wait_group 1;\n");
            } else {
                asm volatile("cp.async.wait_group 0;\n");
            }
            __syncthreads();

            float4 ha[4];
#pragma unroll
            for (int i = 0; i < 4; i++)
                ha[i] = *(const float4*)&cur[(bg * 4 + i) * 64 + ks * 4];
#pragma unroll
            for (int cc = 0; cc < 12; cc++) {
                float4 wv = *(const float4*)&Ws[cc * 1024 + c * 64 + ks * 4];
#pragma unroll
                for (int i = 0; i < 4; i++) {
                    acc[i][cc] += ha[i].x * wv.x;
                    acc[i][cc] += ha[i].y * wv.y;
                    acc[i][cc] += ha[i].z * wv.z;
                    acc[i][cc] += ha[i].w * wv.w;
                }
            }
            __syncthreads();
        }

#pragma unroll
        for (int off = 8; off > 0; off >>= 1)
#pragma unroll
            for (int i = 0; i < 4; i++)
#pragma unroll
                for (int cc = 0; cc < 12; cc++)
                    acc[i][cc] += __shfl_xor_sync(0xffffffffu, acc[i][cc], off);

        {
            int bi = ks >> 2, jj = ks & 3;
            float ghr = acc[bi][jj * 3 + 0] + bh_r;
            float ghz = acc[bi][jj * 3 + 1] + bh_z;
            float ghn = acc[bi][jj * 3 + 2] + bh_n;
            float r = 1.0f / (1.0f + expf(-(gi_r + ghr)));
            float z = 1.0f / (1.0f + expf(-(gi_z + ghz)));
            float n = tanhf(gi_n + r * ghn);
            float keep = (s < len_b) ? 1.0f : 0.0f;
            float hnew = (n + z * (h_old - n)) * keep;

            hnxt[b * 1024 + j] = hnew;
            out_hs[(long long)s * (BATCH * 2 * HDIM) + b * (2 * HDIM) + j] = hnew;
            if (s == SEQ - 1) out_hlast[b * 1024 + j] = hnew;
        }

        phase++;
        __threadfence(); __syncthreads();
        if (tid == 0) {
            atomicAdd(bar, 1u);
            while (*((volatile unsigned*)bar) < phase * RBLOCKS) { __nanosleep(32); }
        }
        __syncthreads();
    }
}

// =====================================================================
// Softmax — unchanged
// =====================================================================
__global__ void attn_softmax_kernel(const float* __restrict__ scores,   // [b][s][l]
                                    const int* __restrict__ post_length,
                                    float* __restrict__ attn_scratch,   // [b][s][l]
                                    float* __restrict__ out_attn)       // [s][l][b]
{
    int s = blockIdx.x;
    int b = blockIdx.y;
    int l = threadIdx.x;

    float sc = scores[((long long)b * SEQ + s) * PLEN + l];
    if (l >= post_length[b]) sc = -1000000000.0f;

    __shared__ float red[PLEN];
    red[l] = sc;
    __syncthreads();
#pragma unroll
    for (int o = PLEN / 2; o > 0; o >>= 1) {
        if (l < o) red[l] = fmaxf(red[l], red[l + o]);
        __syncthreads();
    }
    float mx = red[0];
    __syncthreads();

    float e = expf(sc - mx);
    red[l] = e;
    __syncthreads();
#pragma unroll
    for (int o = PLEN / 2; o > 0; o >>= 1) {
        if (l < o) red[l] += red[l + o];
        __syncthreads();
    }
    float a = e / red[0];

    attn_scratch[((long long)b * SEQ + s) * PLEN + l] = a;
    out_attn[(long long)s * (PLEN * BATCH) + l * BATCH + b] = a;
}

// =====================================================================
// launch
// =====================================================================
extern "C" void kernel_launch(void* const* d_in, const int* in_sizes, int n_in,
                              void* d_out, int out_size)
{
    (void)in_sizes; (void)n_in; (void)out_size;

    const float* incoming = (const float*)d_in[0];
    const float* post     = (const float*)d_in[1];
    const float* h_init   = (const float*)d_in[2];
    const float* W_ih     = (const float*)d_in[3];
    const float* W_hh     = (const float*)d_in[4];
    const float* b_ih     = (const float*)d_in[5];
    const float* b_hh     = (const float*)d_in[6];
    const float* Wq       = (const float*)d_in[7];
    const float* bq       = (const float*)d_in[8];
    const int*   length      = (const int*)d_in[9];
    const int*   post_length = (const int*)d_in[10];

    float* out       = (float*)d_out;
    float* out_hlast = out;                                   // [B, H]
    float* out_hs    = out + BATCH * HDIM;                    // [S, B, 2H]
    float* out_attn  = out_hs + (long long)SEQ * BATCH * 2 * HDIM;  // [S, PL, B]

    float *gi, *h2, *query, *scores, *attn;
    float2 *Wih2, *Wq2;
    unsigned* bar;
    cudaGetSymbolAddress((void**)&gi,     g_gi);
    cudaGetSymbolAddress((void**)&h2,     g_h2);
    cudaGetSymbolAddress((void**)&query,  g_query);
    cudaGetSymbolAddress((void**)&scores, g_scores);
    cudaGetSymbolAddress((void**)&attn,   g_attn);
    cudaGetSymbolAddress((void**)&Wih2,   g_Wih2);
    cudaGetSymbolAddress((void**)&Wq2,    g_Wq2);
    cudaGetSymbolAddress((void**)&bar,    g_bar);

    cudaFuncSetAttribute(gru_persistent,
                         cudaFuncAttributeMaxDynamicSharedMemorySize, 81920);
    cudaFuncSetAttribute(tgemm_nt_ws,
                         cudaFuncAttributeMaxDynamicSharedMemorySize, WS_SMEM);

    const int MALL = SEQ * BATCH;   // 16384

    // Prep: split weight matrices once per launch (cheap elementwise)
    split_w<<<(3 * HDIM * IDIM + 255) / 256, 256>>>(W_ih, Wih2, 3 * HDIM * IDIM);
    split_w<<<(PDIM * HDIM + 255) / 256, 256>>>(Wq, Wq2, PDIM * HDIM);

    // Phase A: gi = incoming @ W_ih^T + b_ih  [16384, 3072] k=1024 (split W)
    tgemm_nt_ws<<<dim3(3 * HDIM / 128, MALL / 128), 256, WS_SMEM>>>(
        MALL, 3 * HDIM, IDIM,
        incoming, IDIM,
        Wih2, IDIM,
        gi, 3 * HDIM,
        b_ih);

    // Phase B: persistent fused GRU recurrence (scalar FFMA, proven)
    cudaMemsetAsync(bar, 0, sizeof(unsigned));
    gru_persistent<<<RBLOCKS, RTHREADS, 81920>>>(
        gi, W_hh, b_hh, h_init, length, h2, out_hs, out_hlast, bar);

    // Phase C: query = h_all @ Wq^T + bq (h from hs region, stride 2H; split W)
    tgemm_nt_ws<<<dim3(PDIM / 128, MALL / 128), 256, WS_SMEM>>>(
        MALL, PDIM, HDIM,
        out_hs, 2 * HDIM,
        Wq2, HDIM,
        query, PDIM,
        bq);

    // Phase D1: scores_b = Q_b @ post_b^T (batched over b)
    tgemm_nt<<<dim3(PLEN / 128, SEQ / 128, BATCH), 256>>>(
        SEQ, PLEN, PDIM,
        query, (long long)BATCH * PDIM, PDIM,
        post, (long long)BATCH * PDIM, PDIM,
        scores, PLEN, (long long)SEQ * PLEN,
        (const float*)nullptr);

    // Phase D2: masked softmax over l
    attn_softmax_kernel<<<dim3(SEQ, BATCH), PLEN>>>(scores, post_length, attn, out_attn);

    // Phase D3: context_b = attn_b @ post_b
    tgemm_nn<<<dim3(PDIM / 128, SEQ / 128, BATCH), 256>>>(
        SEQ, PDIM, PLEN,
        attn, PLEN, (long long)SEQ * PLEN,
        post, (long long)BATCH * PDIM, PDIM,
        out_hs + HDIM, (long long)BATCH * 2 * HDIM, 2 * HDIM);
}

// round 14
// speedup vs baseline: 3.0788x; 1.3654x over previous
#include <cuda_runtime.h>
#include <math.h>

// Problem dims
#define SEQ   256
#define BATCH 64
#define IDIM  1024
#define HDIM  1024
#define PLEN  256
#define PDIM  1024

#define RBLOCKS  256
#define RTHREADS 256

// -------- device scratch (no runtime allocation allowed) --------
__device__ __align__(16) float g_gi[SEQ * BATCH * 3 * HDIM];   // precomputed input gates
__device__ __align__(16) float g_h2[2 * BATCH * HDIM];         // double-buffered hidden state
__device__ float g_query[SEQ * BATCH * PDIM];
__device__ float g_scores[BATCH * SEQ * PLEN];
__device__ float g_attn[BATCH * SEQ * PLEN];
__device__ unsigned g_bar;                                     // grid barrier counter

extern __shared__ float rsm[];

// =====================================================================
// helpers
// =====================================================================
__device__ __forceinline__ void cp_async16(void* smem_dst, const void* gmem_src)
{
    unsigned ds = (unsigned)__cvta_generic_to_shared(smem_dst);
    asm volatile("cp.async.cg.shared.global [%0], [%1], 16;\n" :: "r"(ds), "l"(gmem_src));
}

__device__ __forceinline__ unsigned f2tf(float x)
{
    unsigned r; asm("cvt.rna.tf32.f32 %0, %1;" : "=r"(r) : "f"(x)); return r;
}

__device__ __forceinline__ void mma8(float* c,
                                     unsigned a0, unsigned a1, unsigned a2, unsigned a3,
                                     unsigned b0, unsigned b1)
{
    asm volatile("mma.sync.aligned.m16n8k8.row.col.f32.tf32.tf32.f32 "
                 "{%0,%1,%2,%3},{%4,%5,%6,%7},{%8,%9},{%0,%1,%2,%3};"
                 : "+f"(c[0]), "+f"(c[1]), "+f"(c[2]), "+f"(c[3])
                 : "r"(a0), "r"(a1), "r"(a2), "r"(a3), "r"(b0), "r"(b1));
}

__device__ __forceinline__ float4 ldcg4(const float4* p)
{
    float4 v;
    asm volatile("ld.global.cg.v4.f32 {%0,%1,%2,%3}, [%4];"
                 : "=f"(v.x), "=f"(v.y), "=f"(v.z), "=f"(v.w) : "l"(p));
    return v;
}

// =====================================================================
// Tensor-core tf32 (3xTF32) GEMM, C = A * W^T (+bias) — R8 version
// =====================================================================
__global__ void __launch_bounds__(256)
tgemm_nt(int M, int N, int K,
         const float* __restrict__ A, long long lda, long long bsA,
         const float* __restrict__ W, long long ldw, long long bsW,
         float* __restrict__ C, long long ldc, long long bsC,
         const float* __restrict__ bias)
{
    __shared__ float sA[2][128 * 20];
    __shared__ float sB[2][128 * 20];

    const int tid = threadIdx.x;
    const int n0 = blockIdx.x * 128;
    const int m0 = blockIdx.y * 128;
    A += (long long)blockIdx.z * bsA;
    W += (long long)blockIdx.z * bsW;
    C += (long long)blockIdx.z * bsC;

    const int w    = tid >> 5;
    const int lane = tid & 31;
    const int lq   = lane >> 2;
    const int lr   = lane & 3;
    const int wm   = (w & 3) * 32;
    const int wn   = (w >> 2) * 64;

    float acc[2][8][4];
#pragma unroll
    for (int mt = 0; mt < 2; mt++)
#pragma unroll
        for (int nt = 0; nt < 8; nt++)
#pragma unroll
            for (int i = 0; i < 4; i++) acc[mt][nt][i] = 0.0f;

    const int nkt = K >> 4;

    auto load_stage = [&](int s, int kt) {
#pragma unroll
        for (int i = 0; i < 2; i++) {
            int idx = i * 256 + tid;
            int row = idx >> 2, c4 = idx & 3;
            cp_async16(&sA[s][row * 20 + c4 * 4],
                       A + (long long)(m0 + row) * lda + kt * 16 + c4 * 4);
            cp_async16(&sB[s][row * 20 + c4 * 4],
                       W + (long long)(n0 + row) * ldw + kt * 16 + c4 * 4);
        }
        asm volatile("cp.async.commit_group;\n");
    };

    load_stage(0, 0);

    for (int kt = 0; kt < nkt; kt++) {
        int cur = kt & 1;
        if (kt + 1 < nkt) {
            load_stage(cur ^ 1, kt + 1);
            asm volatile("cp.async.wait_group 1;\n");
        } else {
            asm volatile("cp.async.wait_group 0;\n");
        }
        __syncthreads();

        const float* pA = sA[cur];
        const float* pB = sB[cur];

#pragma unroll
        for (int kl = 0; kl < 16; kl += 8) {
            unsigned ahi[2][4], alo[2][4];
#pragma unroll
            for (int mt = 0; mt < 2; mt++) {
                int rb = wm + mt * 16 + lq;
                float a0 = pA[rb * 20 + kl + lr];
                float a1 = pA[(rb + 8) * 20 + kl + lr];
                float a2 = pA[rb * 20 + kl + lr + 4];
                float a3 = pA[(rb + 8) * 20 + kl + lr + 4];
                ahi[mt][0] = f2tf(a0); alo[mt][0] = f2tf(a0 - __uint_as_float(ahi[mt][0]));
                ahi[mt][1] = f2tf(a1); alo[mt][1] = f2tf(a1 - __uint_as_float(ahi[mt][1]));
                ahi[mt][2] = f2tf(a2); alo[mt][2] = f2tf(a2 - __uint_as_float(ahi[mt][2]));
                ahi[mt][3] = f2tf(a3); alo[mt][3] = f2tf(a3 - __uint_as_float(ahi[mt][3]));
            }
#pragma unroll
            for (int nt = 0; nt < 8; nt++) {
                int nr = wn + nt * 8 + lq;
                float b0 = pB[nr * 20 + kl + lr];
                float b1 = pB[nr * 20 + kl + lr + 4];
                unsigned bh0 = f2tf(b0), bh1 = f2tf(b1);
                unsigned bl0 = f2tf(b0 - __uint_as_float(bh0));
                unsigned bl1 = f2tf(b1 - __uint_as_float(bh1));
#pragma unroll
                for (int mt = 0; mt < 2; mt++) {
                    mma8(acc[mt][nt], alo[mt][0], alo[mt][1], alo[mt][2], alo[mt][3], bh0, bh1);
                    mma8(acc[mt][nt], ahi[mt][0], ahi[mt][1], ahi[mt][2], ahi[mt][3], bl0, bl1);
                    mma8(acc[mt][nt], ahi[mt][0], ahi[mt][1], ahi[mt][2], ahi[mt][3], bh0, bh1);
                }
            }
        }
        __syncthreads();
    }

#pragma unroll
    for (int mt = 0; mt < 2; mt++) {
#pragma unroll
        for (int nt = 0; nt < 8; nt++) {
            int row = m0 + wm + mt * 16 + lq;
            int col = n0 + wn + nt * 8 + lr * 2;
            float bc0 = bias ? bias[col]     : 0.0f;
            float bc1 = bias ? bias[col + 1] : 0.0f;
            float2 v0 = make_float2(acc[mt][nt][0] + bc0, acc[mt][nt][1] + bc1);
            float2 v1 = make_float2(acc[mt][nt][2] + bc0, acc[mt][nt][3] + bc1);
            *(float2*)&C[(long long)row * ldc + col]       = v0;
            *(float2*)&C[(long long)(row + 8) * ldc + col] = v1;
        }
    }
}

// =====================================================================
// Tensor-core tf32 (3xTF32) GEMM, C = A * B — R8 version
// =====================================================================
__global__ void __launch_bounds__(256)
tgemm_nn(int M, int N, int K,
         const float* __restrict__ A, long long lda, long long bsA,
         const float* __restrict__ B, long long ldb, long long bsB,
         float* __restrict__ C, long long ldc, long long bsC)
{
    __shared__ float sA[2][128 * 20];
    __shared__ float sB[2][16 * 132];

    const int tid = threadIdx.x;
    const int n0 = blockIdx.x * 128;
    const int m0 = blockIdx.y * 128;
    A += (long long)blockIdx.z * bsA;
    B += (long long)blockIdx.z * bsB;
    C += (long long)blockIdx.z * bsC;

    const int w    = tid >> 5;
    const int lane = tid & 31;
    const int lq   = lane >> 2;
    const int lr   = lane & 3;
    const int wm   = (w & 3) * 32;
    const int wn   = (w >> 2) * 64;

    float acc[2][8][4];
#pragma unroll
    for (int mt = 0; mt < 2; mt++)
#pragma unroll
        for (int nt = 0; nt < 8; nt++)
#pragma unroll
            for (int i = 0; i < 4; i++) acc[mt][nt][i] = 0.0f;

    const int nkt = K >> 4;

    auto load_stage = [&](int s, int kt) {
#pragma unroll
        for (int i = 0; i < 2; i++) {
            int idx = i * 256 + tid;
            int row = idx >> 2, c4 = idx & 3;
            cp_async16(&sA[s][row * 20 + c4 * 4],
                       A + (long long)(m0 + row) * lda + kt * 16 + c4 * 4);
            int kr = idx >> 5, nc = idx & 31;
            cp_async16(&sB[s][kr * 132 + nc * 4],
                       B + (long long)(kt * 16 + kr) * ldb + n0 + nc * 4);
        }
        asm volatile("cp.async.commit_group;\n");
    };

    load_stage(0, 0);

    for (int kt = 0; kt < nkt; kt++) {
        int cur = kt & 1;
        if (kt + 1 < nkt) {
            load_stage(cur ^ 1, kt + 1);
            asm volatile("cp.async.wait_group 1;\n");
        } else {
            asm volatile("cp.async.wait_group 0;\n");
        }
        __syncthreads();

        const float* pA = sA[cur];
        const float* pB = sB[cur];

#pragma unroll
        for (int kl = 0; kl < 16; kl += 8) {
            unsigned ahi[2][4], alo[2][4];
#pragma unroll
            for (int mt = 0; mt < 2; mt++) {
                int rb = wm + mt * 16 + lq;
                float a0 = pA[rb * 20 + kl + lr];
                float a1 = pA[(rb + 8) * 20 + kl + lr];
                float a2 = pA[rb * 20 + kl + lr + 4];
                float a3 = pA[(rb + 8) * 20 + kl + lr + 4];
                ahi[mt][0] = f2tf(a0); alo[mt][0] = f2tf(a0 - __uint_as_float(ahi[mt][0]));
                ahi[mt][1] = f2tf(a1); alo[mt][1] = f2tf(a1 - __uint_as_float(ahi[mt][1]));
                ahi[mt][2] = f2tf(a2); alo[mt][2] = f2tf(a2 - __uint_as_float(ahi[mt][2]));
                ahi[mt][3] = f2tf(a3); alo[mt][3] = f2tf(a3 - __uint_as_float(ahi[mt][3]));
            }
#pragma unroll
            for (int nt = 0; nt < 8; nt++) {
                int nc = wn + nt * 8 + lq;
                float b0 = pB[(kl + lr) * 132 + nc];
                float b1 = pB[(kl + lr + 4) * 132 + nc];
                unsigned bh0 = f2tf(b0), bh1 = f2tf(b1);
                unsigned bl0 = f2tf(b0 - __uint_as_float(bh0));
                unsigned bl1 = f2tf(b1 - __uint_as_float(bh1));
#pragma unroll
                for (int mt = 0; mt < 2; mt++) {
                    mma8(acc[mt][nt], alo[mt][0], alo[mt][1], alo[mt][2], alo[mt][3], bh0, bh1);
                    mma8(acc[mt][nt], ahi[mt][0], ahi[mt][1], ahi[mt][2], ahi[mt][3], bl0, bl1);
                    mma8(acc[mt][nt], ahi[mt][0], ahi[mt][1], ahi[mt][2], ahi[mt][3], bh0, bh1);
                }
            }
        }
        __syncthreads();
    }

#pragma unroll
    for (int mt = 0; mt < 2; mt++) {
#pragma unroll
        for (int nt = 0; nt < 8; nt++) {
            int row = m0 + wm + mt * 16 + lq;
            int col = n0 + wn + nt * 8 + lr * 2;
            *(float2*)&C[(long long)row * ldc + col] =
                make_float2(acc[mt][nt][0], acc[mt][nt][1]);
            *(float2*)&C[(long long)(row + 8) * ldc + col] =
                make_float2(acc[mt][nt][2], acc[mt][nt][3]);
        }
    }
}

// =====================================================================
// Persistent GRU recurrence — direct-L2 h loads, no h staging.
//   256 blocks x 256 threads, 2/SM. Block owns 4 hidden cols j
//   (12 W_hh rows stationary in smem, loaded once). Thread (bg, ks):
//   bg = tid/16 owns batches [4bg,4bg+4), ks = tid%16 owns k-slice
//   {c*64 + ks*4 ..+3}. Each h element is consumed by exactly ONE
//   thread in the block, so h is read straight from L2 (__ldcg float4,
//   register double-buffered) — no smem, no per-chunk __syncthreads.
//   16-lane shuffle butterfly reduce, fused gates, grid barrier per step.
// =====================================================================
__global__ void __launch_bounds__(RTHREADS, 2)
gru_persistent(const float* __restrict__ gi,
               const float* __restrict__ W_hh,
               const float* __restrict__ b_hh,
               const float* __restrict__ h_init,
               const int* __restrict__ length,
               float* __restrict__ h2,          // [2][B*H]
               float* __restrict__ out_hs,      // [S][B][2H]
               float* __restrict__ out_hlast,   // [B][H]
               unsigned* __restrict__ bar)
{
    const int tid = threadIdx.x;
    const int bg  = tid >> 4;        // 0..15 -> batches [4bg, 4bg+4)
    const int ks  = tid & 15;        // k-slice / gate-lane id
    const int j0  = blockIdx.x * 4;
    const int b   = bg * 4 + (ks >> 2);
    const int j   = j0 + (ks & 3);

    float* Ws = rsm;                 // 12 x 1024 floats, stationary

    // ---- load stationary W_hh slice (cc = jj*3 + g -> row g*1024 + j0 + jj)
    for (int v = tid; v < 12 * 256; v += RTHREADS) {
        int cc = v >> 8;
        int cq = v & 255;
        int row = (cc % 3) * 1024 + j0 + (cc / 3);
        ((float4*)Ws)[cc * 256 + cq] = ((const float4*)W_hh)[row * 256 + cq];
    }

    const float bh_r = b_hh[j];
    const float bh_z = b_hh[1024 + j];
    const float bh_n = b_hh[2048 + j];
    const int   len_b = length[b];

    // ---- init h buffer 0 (grid covers exactly 64*1024 elements)
    {
        int v = blockIdx.x * RTHREADS + tid;
        h2[v] = h_init[v & (HDIM - 1)];
    }

    // W smem + h init visible before compute
    unsigned phase = 1;
    {
        __threadfence(); __syncthreads();
        if (tid == 0) {
            atomicAdd(bar, 1u);
            while (*((volatile unsigned*)bar) < phase * RBLOCKS) { __nanosleep(32); }
        }
        __syncthreads();
    }

    for (int s = 0; s < SEQ; s++) {
        const float* hcur = h2 + (s & 1) * (BATCH * HDIM);
        float*       hnxt = h2 + ((s + 1) & 1) * (BATCH * HDIM);
        // thread's own float4 row pointers: hc4[(4bg+i)*256 + c*16 + ks]
        const float4* hc4 = (const float4*)hcur;

        // prefetch gi + h_old (consumed in gates)
        const float* gis = gi + (long long)s * (BATCH * 3 * HDIM) + b * 3 * HDIM;
        float gi_r  = __ldg(&gis[j]);
        float gi_z  = __ldg(&gis[1024 + j]);
        float gi_n  = __ldg(&gis[2048 + j]);
        float h_old = __ldcg(&hcur[b * 1024 + j]);

        float acc[4][12];
#pragma unroll
        for (int i = 0; i < 4; i++)
#pragma unroll
            for (int cc = 0; cc < 12; cc++) acc[i][cc] = 0.0f;

        // register double-buffered direct L2 loads of this thread's h slice
        float4 hcurb[4], hnxtb[4];
#pragma unroll
        for (int i = 0; i < 4; i++)
            hcurb[i] = ldcg4(&hc4[(bg * 4 + i) * 256 + ks]);

        for (int c = 0; c < 16; c++) {
            if (c + 1 < 16) {
#pragma unroll
                for (int i = 0; i < 4; i++)
                    hnxtb[i] = ldcg4(&hc4[(bg * 4 + i) * 256 + (c + 1) * 16 + ks]);
            }
#pragma unroll
            for (int cc = 0; cc < 12; cc++) {
                float4 wv = *(const float4*)&Ws[cc * 1024 + c * 64 + ks * 4];
#pragma unroll
                for (int i = 0; i < 4; i++) {
                    acc[i][cc] += hcurb[i].x * wv.x;
                    acc[i][cc] += hcurb[i].y * wv.y;
                    acc[i][cc] += hcurb[i].z * wv.z;
                    acc[i][cc] += hcurb[i].w * wv.w;
                }
            }
#pragma unroll
            for (int i = 0; i < 4; i++) hcurb[i] = hnxtb[i];
        }

        // butterfly reduce over 16 k-slices (stays within 16-lane halves)
#pragma unroll
        for (int off = 8; off > 0; off >>= 1)
#pragma unroll
            for (int i = 0; i < 4; i++)
#pragma unroll
                for (int cc = 0; cc < 12; cc++)
                    acc[i][cc] += __shfl_xor_sync(0xffffffffu, acc[i][cc], off);

        // fused gates: lane handles (b, j)
        {
            int bi = ks >> 2, jj = ks & 3;
            float ghr = acc[bi][jj * 3 + 0] + bh_r;
            float ghz = acc[bi][jj * 3 + 1] + bh_z;
            float ghn = acc[bi][jj * 3 + 2] + bh_n;
            float r = 1.0f / (1.0f + expf(-(gi_r + ghr)));
            float z = 1.0f / (1.0f + expf(-(gi_z + ghz)));
            float n = tanhf(gi_n + r * ghn);
            float keep = (s < len_b) ? 1.0f : 0.0f;
            float hnew = (n + z * (h_old - n)) * keep;

            hnxt[b * 1024 + j] = hnew;
            out_hs[(long long)s * (BATCH * 2 * HDIM) + b * (2 * HDIM) + j] = hnew;
            if (s == SEQ - 1) out_hlast[b * 1024 + j] = hnew;
        }

        // end-of-step grid barrier
        phase++;
        __threadfence(); __syncthreads();
        if (tid == 0) {
            atomicAdd(bar, 1u);
            while (*((volatile unsigned*)bar) < phase * RBLOCKS) { __nanosleep(32); }
        }
        __syncthreads();
    }
}

// =====================================================================
// Softmax — unchanged
// =====================================================================
__global__ void attn_softmax_kernel(const float* __restrict__ scores,   // [b][s][l]
                                    const int* __restrict__ post_length,
                                    float* __restrict__ attn_scratch,   // [b][s][l]
                                    float* __restrict__ out_attn)       // [s][l][b]
{
    int s = blockIdx.x;
    int b = blockIdx.y;
    int l = threadIdx.x;

    float sc = scores[((long long)b * SEQ + s) * PLEN + l];
    if (l >= post_length[b]) sc = -1000000000.0f;

    __shared__ float red[PLEN];
    red[l] = sc;
    __syncthreads();
#pragma unroll
    for (int o = PLEN / 2; o > 0; o >>= 1) {
        if (l < o) red[l] = fmaxf(red[l], red[l + o]);
        __syncthreads();
    }
    float mx = red[0];
    __syncthreads();

    float e = expf(sc - mx);
    red[l] = e;
    __syncthreads();
#pragma unroll
    for (int o = PLEN / 2; o > 0; o >>= 1) {
        if (l < o) red[l] += red[l + o];
        __syncthreads();
    }
    float a = e / red[0];

    attn_scratch[((long long)b * SEQ + s) * PLEN + l] = a;
    out_attn[(long long)s * (PLEN * BATCH) + l * BATCH + b] = a;
}

// =====================================================================
// launch
// =====================================================================
extern "C" void kernel_launch(void* const* d_in, const int* in_sizes, int n_in,
                              void* d_out, int out_size)
{
    (void)in_sizes; (void)n_in; (void)out_size;

    const float* incoming = (const float*)d_in[0];
    const float* post     = (const float*)d_in[1];
    const float* h_init   = (const float*)d_in[2];
    const float* W_ih     = (const float*)d_in[3];
    const float* W_hh     = (const float*)d_in[4];
    const float* b_ih     = (const float*)d_in[5];
    const float* b_hh     = (const float*)d_in[6];
    const float* Wq       = (const float*)d_in[7];
    const float* bq       = (const float*)d_in[8];
    const int*   length      = (const int*)d_in[9];
    const int*   post_length = (const int*)d_in[10];

    float* out       = (float*)d_out;
    float* out_hlast = out;                                   // [B, H]
    float* out_hs    = out + BATCH * HDIM;                    // [S, B, 2H]
    float* out_attn  = out_hs + (long long)SEQ * BATCH * 2 * HDIM;  // [S, PL, B]

    float *gi, *h2, *query, *scores, *attn;
    unsigned* bar;
    cudaGetSymbolAddress((void**)&gi,     g_gi);
    cudaGetSymbolAddress((void**)&h2,     g_h2);
    cudaGetSymbolAddress((void**)&query,  g_query);
    cudaGetSymbolAddress((void**)&scores, g_scores);
    cudaGetSymbolAddress((void**)&attn,   g_attn);
    cudaGetSymbolAddress((void**)&bar,    g_bar);

    cudaFuncSetAttribute(gru_persistent,
                         cudaFuncAttributeMaxDynamicSharedMemorySize, 49152);

    const int MALL = SEQ * BATCH;   // 16384

    // Phase A: gi = incoming @ W_ih^T + b_ih  [16384, 3072] k=1024
    tgemm_nt<<<dim3(3 * HDIM / 128, MALL / 128), 256>>>(
        MALL, 3 * HDIM, IDIM,
        incoming, IDIM, 0,
        W_ih, IDIM, 0,
        gi, 3 * HDIM, 0,
        b_ih);

    // Phase B: persistent fused GRU recurrence (direct-L2 h loads)
    cudaMemsetAsync(bar, 0, sizeof(unsigned));
    gru_persistent<<<RBLOCKS, RTHREADS, 49152>>>(
        gi, W_hh, b_hh, h_init, length, h2, out_hs, out_hlast, bar);

    // Phase C: query = h_all @ Wq^T + bq (h read from hs region, stride 2H)
    tgemm_nt<<<dim3(PDIM / 128, MALL / 128), 256>>>(
        MALL, PDIM, HDIM,
        out_hs, 2 * HDIM, 0,
        Wq, HDIM, 0,
        query, PDIM, 0,
        bq);

    // Phase D1: scores_b = Q_b @ post_b^T (batched over b)
    tgemm_nt<<<dim3(PLEN / 128, SEQ / 128, BATCH), 256>>>(
        SEQ, PLEN, PDIM,
        query, (long long)BATCH * PDIM, PDIM,
        post, (long long)BATCH * PDIM, PDIM,
        scores, PLEN, (long long)SEQ * PLEN,
        (const float*)nullptr);

    // Phase D2: masked softmax over l
    attn_softmax_kernel<<<dim3(SEQ, BATCH), PLEN>>>(scores, post_length, attn, out_attn);

    // Phase D3: context_b = attn_b @ post_b
    tgemm_nn<<<dim3(PDIM / 128, SEQ / 128, BATCH), 256>>>(
        SEQ, PDIM, PLEN,
        attn, PLEN, (long long)SEQ * PLEN,
        post, (long long)BATCH * PDIM, PDIM,
        out_hs + HDIM, (long long)BATCH * 2 * HDIM, 2 * HDIM);
}

// round 16
// speedup vs baseline: 3.6057x; 1.1711x over previous
#include <cuda_runtime.h>
#include <math.h>

// Problem dims
#define SEQ   256
#define BATCH 64
#define IDIM  1024
#define HDIM  1024
#define PLEN  256
#define PDIM  1024

#define RBLOCKS  256
#define RTHREADS 256

// -------- device scratch (no runtime allocation allowed) --------
__device__ __align__(16) float g_gi[SEQ * BATCH * 3 * HDIM];   // precomputed input gates
__device__ __align__(16) float g_h2[2 * BATCH * HDIM];         // double-buffered hidden state
__device__ float g_query[SEQ * BATCH * PDIM];
__device__ float g_scores[BATCH * SEQ * PLEN];
__device__ float g_attn[BATCH * SEQ * PLEN];
__device__ unsigned g_bar;                                     // grid barrier counter

extern __shared__ float rsm[];

// =====================================================================
// helpers
// =====================================================================
__device__ __forceinline__ void cp_async16(void* smem_dst, const void* gmem_src)
{
    unsigned ds = (unsigned)__cvta_generic_to_shared(smem_dst);
    asm volatile("cp.async.cg.shared.global [%0], [%1], 16;\n" :: "r"(ds), "l"(gmem_src));
}

// split two f32 (x0 = lower k index, x1 = higher) into packed bf16x2 hi/lo
__device__ __forceinline__ void bsplit2(float x0, float x1, unsigned& hi, unsigned& lo)
{
    unsigned h;
    asm("cvt.rn.bf16x2.f32 %0, %1, %2;" : "=r"(h) : "f"(x1), "f"(x0));
    float h0 = __uint_as_float(h << 16);
    float h1 = __uint_as_float(h & 0xffff0000u);
    float l0 = x0 - h0;
    float l1 = x1 - h1;
    unsigned l;
    asm("cvt.rn.bf16x2.f32 %0, %1, %2;" : "=r"(l) : "f"(l1), "f"(l0));
    hi = h; lo = l;
}

// mma m16n8k16 bf16 -> f32
__device__ __forceinline__ void mma16(float* c,
                                      unsigned a0, unsigned a1, unsigned a2, unsigned a3,
                                      unsigned b0, unsigned b1)
{
    asm volatile("mma.sync.aligned.m16n8k16.row.col.f32.bf16.bf16.f32 "
                 "{%0,%1,%2,%3},{%4,%5,%6,%7},{%8,%9},{%0,%1,%2,%3};"
                 : "+f"(c[0]), "+f"(c[1]), "+f"(c[2]), "+f"(c[3])
                 : "r"(a0), "r"(a1), "r"(a2), "r"(a3), "r"(b0), "r"(b1));
}

__device__ __forceinline__ float4 ldcg4(const float4* p)
{
    float4 v;
    asm volatile("ld.global.cg.v4.f32 {%0,%1,%2,%3}, [%4];"
                 : "=f"(v.x), "=f"(v.y), "=f"(v.z), "=f"(v.w) : "l"(p));
    return v;
}

// =====================================================================
// Tensor-core 3xBF16 GEMM, C = A * W^T (+bias)
//   A [M,K] rows stride lda;  W [N,K] rows stride ldw. 128x128x16 tiles,
//   8 warps (4M x 2N), 2-stage cp.async. smem [row][k] stride 20.
//   m16n8k16 bf16 mma, 3 error-compensated passes (lo*hi + hi*lo + hi*hi).
// =====================================================================
__global__ void __launch_bounds__(256)
tgemm_nt(int M, int N, int K,
         const float* __restrict__ A, long long lda, long long bsA,
         const float* __restrict__ W, long long ldw, long long bsW,
         float* __restrict__ C, long long ldc, long long bsC,
         const float* __restrict__ bias)
{
    __shared__ float sA[2][128 * 20];
    __shared__ float sB[2][128 * 20];

    const int tid = threadIdx.x;
    const int n0 = blockIdx.x * 128;
    const int m0 = blockIdx.y * 128;
    A += (long long)blockIdx.z * bsA;
    W += (long long)blockIdx.z * bsW;
    C += (long long)blockIdx.z * bsC;

    const int w    = tid >> 5;
    const int lane = tid & 31;
    const int lq   = lane >> 2;
    const int lr   = lane & 3;
    const int wm   = (w & 3) * 32;
    const int wn   = (w >> 2) * 64;

    float acc[2][8][4];
#pragma unroll
    for (int mt = 0; mt < 2; mt++)
#pragma unroll
        for (int nt = 0; nt < 8; nt++)
#pragma unroll
            for (int i = 0; i < 4; i++) acc[mt][nt][i] = 0.0f;

    const int nkt = K >> 4;

    auto load_stage = [&](int s, int kt) {
#pragma unroll
        for (int i = 0; i < 2; i++) {
            int idx = i * 256 + tid;
            int row = idx >> 2, c4 = idx & 3;
            cp_async16(&sA[s][row * 20 + c4 * 4],
                       A + (long long)(m0 + row) * lda + kt * 16 + c4 * 4);
            cp_async16(&sB[s][row * 20 + c4 * 4],
                       W + (long long)(n0 + row) * ldw + kt * 16 + c4 * 4);
        }
        asm volatile("cp.async.commit_group;\n");
    };

    load_stage(0, 0);

    for (int kt = 0; kt < nkt; kt++) {
        int cur = kt & 1;
        if (kt + 1 < nkt) {
            load_stage(cur ^ 1, kt + 1);
            asm volatile("cp.async.wait_group 1;\n");
        } else {
            asm volatile("cp.async.wait_group 0;\n");
        }
        __syncthreads();

        const float* pA = sA[cur];
        const float* pB = sB[cur];

        // A fragments: m16n8k16 -> a0..a3 bf16x2 pairs
        unsigned ahi[2][4], alo[2][4];
#pragma unroll
        for (int mt = 0; mt < 2; mt++) {
            int rb = wm + mt * 16 + lq;
            float2 p0 = *(const float2*)&pA[rb * 20 + 2 * lr];
            float2 p1 = *(const float2*)&pA[(rb + 8) * 20 + 2 * lr];
            float2 p2 = *(const float2*)&pA[rb * 20 + 8 + 2 * lr];
            float2 p3 = *(const float2*)&pA[(rb + 8) * 20 + 8 + 2 * lr];
            bsplit2(p0.x, p0.y, ahi[mt][0], alo[mt][0]);
            bsplit2(p1.x, p1.y, ahi[mt][1], alo[mt][1]);
            bsplit2(p2.x, p2.y, ahi[mt][2], alo[mt][2]);
            bsplit2(p3.x, p3.y, ahi[mt][3], alo[mt][3]);
        }
#pragma unroll
        for (int nt = 0; nt < 8; nt++) {
            int nr = wn + nt * 8 + lq;
            float2 q0 = *(const float2*)&pB[nr * 20 + 2 * lr];
            float2 q1 = *(const float2*)&pB[nr * 20 + 8 + 2 * lr];
            unsigned bh0, bl0, bh1, bl1;
            bsplit2(q0.x, q0.y, bh0, bl0);
            bsplit2(q1.x, q1.y, bh1, bl1);
#pragma unroll
            for (int mt = 0; mt < 2; mt++) {
                mma16(acc[mt][nt], alo[mt][0], alo[mt][1], alo[mt][2], alo[mt][3], bh0, bh1);
                mma16(acc[mt][nt], ahi[mt][0], ahi[mt][1], ahi[mt][2], ahi[mt][3], bl0, bl1);
                mma16(acc[mt][nt], ahi[mt][0], ahi[mt][1], ahi[mt][2], ahi[mt][3], bh0, bh1);
            }
        }
        __syncthreads();
    }

#pragma unroll
    for (int mt = 0; mt < 2; mt++) {
#pragma unroll
        for (int nt = 0; nt < 8; nt++) {
            int row = m0 + wm + mt * 16 + lq;
            int col = n0 + wn + nt * 8 + lr * 2;
            float bc0 = bias ? bias[col]     : 0.0f;
            float bc1 = bias ? bias[col + 1] : 0.0f;
            float2 v0 = make_float2(acc[mt][nt][0] + bc0, acc[mt][nt][1] + bc1);
            float2 v1 = make_float2(acc[mt][nt][2] + bc0, acc[mt][nt][3] + bc1);
            *(float2*)&C[(long long)row * ldc + col]       = v0;
            *(float2*)&C[(long long)(row + 8) * ldc + col] = v1;
        }
    }
}

// =====================================================================
// Tensor-core 3xBF16 GEMM, C = A * B
//   A [M,K] rows stride lda; B [K,N] rows stride ldb (N contiguous).
// =====================================================================
__global__ void __launch_bounds__(256)
tgemm_nn(int M, int N, int K,
         const float* __restrict__ A, long long lda, long long bsA,
         const float* __restrict__ B, long long ldb, long long bsB,
         float* __restrict__ C, long long ldc, long long bsC)
{
    __shared__ float sA[2][128 * 20];
    __shared__ float sB[2][16 * 132];

    const int tid = threadIdx.x;
    const int n0 = blockIdx.x * 128;
    const int m0 = blockIdx.y * 128;
    A += (long long)blockIdx.z * bsA;
    B += (long long)blockIdx.z * bsB;
    C += (long long)blockIdx.z * bsC;

    const int w    = tid >> 5;
    const int lane = tid & 31;
    const int lq   = lane >> 2;
    const int lr   = lane & 3;
    const int wm   = (w & 3) * 32;
    const int wn   = (w >> 2) * 64;

    float acc[2][8][4];
#pragma unroll
    for (int mt = 0; mt < 2; mt++)
#pragma unroll
        for (int nt = 0; nt < 8; nt++)
#pragma unroll
            for (int i = 0; i < 4; i++) acc[mt][nt][i] = 0.0f;

    const int nkt = K >> 4;

    auto load_stage = [&](int s, int kt) {
#pragma unroll
        for (int i = 0; i < 2; i++) {
            int idx = i * 256 + tid;
            int row = idx >> 2, c4 = idx & 3;
            cp_async16(&sA[s][row * 20 + c4 * 4],
                       A + (long long)(m0 + row) * lda + kt * 16 + c4 * 4);
            int kr = idx >> 5, nc = idx & 31;
            cp_async16(&sB[s][kr * 132 + nc * 4],
                       B + (long long)(kt * 16 + kr) * ldb + n0 + nc * 4);
        }
        asm volatile("cp.async.commit_group;\n");
    };

    load_stage(0, 0);

    for (int kt = 0; kt < nkt; kt++) {
        int cur = kt & 1;
        if (kt + 1 < nkt) {
            load_stage(cur ^ 1, kt + 1);
            asm volatile("cp.async.wait_group 1;\n");
        } else {
            asm volatile("cp.async.wait_group 0;\n");
        }
        __syncthreads();

        const float* pA = sA[cur];
        const float* pB = sB[cur];

        unsigned ahi[2][4], alo[2][4];
#pragma unroll
        for (int mt = 0; mt < 2; mt++) {
            int rb = wm + mt * 16 + lq;
            float2 p0 = *(const float2*)&pA[rb * 20 + 2 * lr];
            float2 p1 = *(const float2*)&pA[(rb + 8) * 20 + 2 * lr];
            float2 p2 = *(const float2*)&pA[rb * 20 + 8 + 2 * lr];
            float2 p3 = *(const float2*)&pA[(rb + 8) * 20 + 8 + 2 * lr];
            bsplit2(p0.x, p0.y, ahi[mt][0], alo[mt][0]);
            bsplit2(p1.x, p1.y, ahi[mt][1], alo[mt][1]);
            bsplit2(p2.x, p2.y, ahi[mt][2], alo[mt][2]);
            bsplit2(p3.x, p3.y, ahi[mt][3], alo[mt][3]);
        }
#pragma unroll
        for (int nt = 0; nt < 8; nt++) {
            int nc = wn + nt * 8 + lq;
            float b00 = pB[(2 * lr) * 132 + nc];
            float b01 = pB[(2 * lr + 1) * 132 + nc];
            float b10 = pB[(8 + 2 * lr) * 132 + nc];
            float b11 = pB[(8 + 2 * lr + 1) * 132 + nc];
            unsigned bh0, bl0, bh1, bl1;
            bsplit2(b00, b01, bh0, bl0);
            bsplit2(b10, b11, bh1, bl1);
#pragma unroll
            for (int mt = 0; mt < 2; mt++) {
                mma16(acc[mt][nt], alo[mt][0], alo[mt][1], alo[mt][2], alo[mt][3], bh0, bh1);
                mma16(acc[mt][nt], ahi[mt][0], ahi[mt][1], ahi[mt][2], ahi[mt][3], bl0, bl1);
                mma16(acc[mt][nt], ahi[mt][0], ahi[mt][1], ahi[mt][2], ahi[mt][3], bh0, bh1);
            }
        }
        __syncthreads();
    }

#pragma unroll
    for (int mt = 0; mt < 2; mt++) {
#pragma unroll
        for (int nt = 0; nt < 8; nt++) {
            int row = m0 + wm + mt * 16 + lq;
            int col = n0 + wn + nt * 8 + lr * 2;
            *(float2*)&C[(long long)row * ldc + col] =
                make_float2(acc[mt][nt][0], acc[mt][nt][1]);
            *(float2*)&C[(long long)(row + 8) * ldc + col] =
                make_float2(acc[mt][nt][2], acc[mt][nt][3]);
        }
    }
}

// =====================================================================
// Persistent GRU recurrence — direct-L2 h loads (R14, proven at FFMA floor)
// =====================================================================
__global__ void __launch_bounds__(RTHREADS, 2)
gru_persistent(const float* __restrict__ gi,
               const float* __restrict__ W_hh,
               const float* __restrict__ b_hh,
               const float* __restrict__ h_init,
               const int* __restrict__ length,
               float* __restrict__ h2,          // [2][B*H]
               float* __restrict__ out_hs,      // [S][B][2H]
               float* __restrict__ out_hlast,   // [B][H]
               unsigned* __restrict__ bar)
{
    const int tid = threadIdx.x;
    const int bg  = tid >> 4;        // 0..15 -> batches [4bg, 4bg+4)
    const int ks  = tid & 15;        // k-slice / gate-lane id
    const int j0  = blockIdx.x * 4;
    const int b   = bg * 4 + (ks >> 2);
    const int j   = j0 + (ks & 3);

    float* Ws = rsm;                 // 12 x 1024 floats, stationary

    for (int v = tid; v < 12 * 256; v += RTHREADS) {
        int cc = v >> 8;
        int cq = v & 255;
        int row = (cc % 3) * 1024 + j0 + (cc / 3);
        ((float4*)Ws)[cc * 256 + cq] = ((const float4*)W_hh)[row * 256 + cq];
    }

    const float bh_r = b_hh[j];
    const float bh_z = b_hh[1024 + j];
    const float bh_n = b_hh[2048 + j];
    const int   len_b = length[b];

    {
        int v = blockIdx.x * RTHREADS + tid;
        h2[v] = h_init[v & (HDIM - 1)];
    }

    unsigned phase = 1;
    {
        __threadfence(); __syncthreads();
        if (tid == 0) {
            atomicAdd(bar, 1u);
            while (*((volatile unsigned*)bar) < phase * RBLOCKS) { __nanosleep(32); }
        }
        __syncthreads();
    }

    for (int s = 0; s < SEQ; s++) {
        const float* hcur = h2 + (s & 1) * (BATCH * HDIM);
        float*       hnxt = h2 + ((s + 1) & 1) * (BATCH * HDIM);
        const float4* hc4 = (const float4*)hcur;

        const float* gis = gi + (long long)s * (BATCH * 3 * HDIM) + b * 3 * HDIM;
        float gi_r  = __ldg(&gis[j]);
        float gi_z  = __ldg(&gis[1024 + j]);
        float gi_n  = __ldg(&gis[2048 + j]);
        float h_old = __ldcg(&hcur[b * 1024 + j]);

        float acc[4][12];
#pragma unroll
        for (int i = 0; i < 4; i++)
#pragma unroll
            for (int cc = 0; cc < 12; cc++) acc[i][cc] = 0.0f;

        float4 hcurb[4], hnxtb[4];
#pragma unroll
        for (int i = 0; i < 4; i++)
            hcurb[i] = ldcg4(&hc4[(bg * 4 + i) * 256 + ks]);

        for (int c = 0; c < 16; c++) {
            if (c + 1 < 16) {
#pragma unroll
                for (int i = 0; i < 4; i++)
                    hnxtb[i] = ldcg4(&hc4[(bg * 4 + i) * 256 + (c + 1) * 16 + ks]);
            }
#pragma unroll
            for (int cc = 0; cc < 12; cc++) {
                float4 wv = *(const float4*)&Ws[cc * 1024 + c * 64 + ks * 4];
#pragma unroll
                for (int i = 0; i < 4; i++) {
                    acc[i][cc] += hcurb[i].x * wv.x;
                    acc[i][cc] += hcurb[i].y * wv.y;
                    acc[i][cc] += hcurb[i].z * wv.z;
                    acc[i][cc] += hcurb[i].w * wv.w;
                }
            }
#pragma unroll
            for (int i = 0; i < 4; i++) hcurb[i] = hnxtb[i];
        }

#pragma unroll
        for (int off = 8; off > 0; off >>= 1)
#pragma unroll
            for (int i = 0; i < 4; i++)
#pragma unroll
                for (int cc = 0; cc < 12; cc++)
                    acc[i][cc] += __shfl_xor_sync(0xffffffffu, acc[i][cc], off);

        {
            int bi = ks >> 2, jj = ks & 3;
            float ghr = acc[bi][jj * 3 + 0] + bh_r;
            float ghz = acc[bi][jj * 3 + 1] + bh_z;
            float ghn = acc[bi][jj * 3 + 2] + bh_n;
            float r = 1.0f / (1.0f + expf(-(gi_r + ghr)));
            float z = 1.0f / (1.0f + expf(-(gi_z + ghz)));
            float n = tanhf(gi_n + r * ghn);
            float keep = (s < len_b) ? 1.0f : 0.0f;
            float hnew = (n + z * (h_old - n)) * keep;

            hnxt[b * 1024 + j] = hnew;
            out_hs[(long long)s * (BATCH * 2 * HDIM) + b * (2 * HDIM) + j] = hnew;
            if (s == SEQ - 1) out_hlast[b * 1024 + j] = hnew;
        }

        phase++;
        __threadfence(); __syncthreads();
        if (tid == 0) {
            atomicAdd(bar, 1u);
            while (*((volatile unsigned*)bar) < phase * RBLOCKS) { __nanosleep(32); }
        }
        __syncthreads();
    }
}

// =====================================================================
// Softmax — unchanged
// =====================================================================
__global__ void attn_softmax_kernel(const float* __restrict__ scores,   // [b][s][l]
                                    const int* __restrict__ post_length,
                                    float* __restrict__ attn_scratch,   // [b][s][l]
                                    float* __restrict__ out_attn)       // [s][l][b]
{
    int s = blockIdx.x;
    int b = blockIdx.y;
    int l = threadIdx.x;

    float sc = scores[((long long)b * SEQ + s) * PLEN + l];
    if (l >= post_length[b]) sc = -1000000000.0f;

    __shared__ float red[PLEN];
    red[l] = sc;
    __syncthreads();
#pragma unroll
    for (int o = PLEN / 2; o > 0; o >>= 1) {
        if (l < o) red[l] = fmaxf(red[l], red[l + o]);
        __syncthreads();
    }
    float mx = red[0];
    __syncthreads();

    float e = expf(sc - mx);
    red[l] = e;
    __syncthreads();
#pragma unroll
    for (int o = PLEN / 2; o > 0; o >>= 1) {
        if (l < o) red[l] += red[l + o];
        __syncthreads();
    }
    float a = e / red[0];

    attn_scratch[((long long)b * SEQ + s) * PLEN + l] = a;
    out_attn[(long long)s * (PLEN * BATCH) + l * BATCH + b] = a;
}

// =====================================================================
// launch
// =====================================================================
extern "C" void kernel_launch(void* const* d_in, const int* in_sizes, int n_in,
                              void* d_out, int out_size)
{
    (void)in_sizes; (void)n_in; (void)out_size;

    const float* incoming = (const float*)d_in[0];
    const float* post     = (const float*)d_in[1];
    const float* h_init   = (const float*)d_in[2];
    const float* W_ih     = (const float*)d_in[3];
    const float* W_hh     = (const float*)d_in[4];
    const float* b_ih     = (const float*)d_in[5];
    const float* b_hh     = (const float*)d_in[6];
    const float* Wq       = (const float*)d_in[7];
    const float* bq       = (const float*)d_in[8];
    const int*   length      = (const int*)d_in[9];
    const int*   post_length = (const int*)d_in[10];

    float* out       = (float*)d_out;
    float* out_hlast = out;                                   // [B, H]
    float* out_hs    = out + BATCH * HDIM;                    // [S, B, 2H]
    float* out_attn  = out_hs + (long long)SEQ * BATCH * 2 * HDIM;  // [S, PL, B]

    float *gi, *h2, *query, *scores, *attn;
    unsigned* bar;
    cudaGetSymbolAddress((void**)&gi,     g_gi);
    cudaGetSymbolAddress((void**)&h2,     g_h2);
    cudaGetSymbolAddress((void**)&query,  g_query);
    cudaGetSymbolAddress((void**)&scores, g_scores);
    cudaGetSymbolAddress((void**)&attn,   g_attn);
    cudaGetSymbolAddress((void**)&bar,    g_bar);

    cudaFuncSetAttribute(gru_persistent,
                         cudaFuncAttributeMaxDynamicSharedMemorySize, 49152);

    const int MALL = SEQ * BATCH;   // 16384

    // Phase A: gi = incoming @ W_ih^T + b_ih  [16384, 3072] k=1024
    tgemm_nt<<<dim3(3 * HDIM / 128, MALL / 128), 256>>>(
        MALL, 3 * HDIM, IDIM,
        incoming, IDIM, 0,
        W_ih, IDIM, 0,
        gi, 3 * HDIM, 0,
        b_ih);

    // Phase B: persistent fused GRU recurrence (direct-L2 h loads)
    cudaMemsetAsync(bar, 0, sizeof(unsigned));
    gru_persistent<<<RBLOCKS, RTHREADS, 49152>>>(
        gi, W_hh, b_hh, h_init, length, h2, out_hs, out_hlast, bar);

    // Phase C: query = h_all @ Wq^T + bq (h read from hs region, stride 2H)
    tgemm_nt<<<dim3(PDIM / 128, MALL / 128), 256>>>(
        MALL, PDIM, HDIM,
        out_hs, 2 * HDIM, 0,
        Wq, HDIM, 0,
        query, PDIM, 0,
        bq);

    // Phase D1: scores_b = Q_b @ post_b^T (batched over b)
    tgemm_nt<<<dim3(PLEN / 128, SEQ / 128, BATCH), 256>>>(
        SEQ, PLEN, PDIM,
        query, (long long)BATCH * PDIM, PDIM,
        post, (long long)BATCH * PDIM, PDIM,
        scores, PLEN, (long long)SEQ * PLEN,
        (const float*)nullptr);

    // Phase D2: masked softmax over l
    attn_softmax_kernel<<<dim3(SEQ, BATCH), PLEN>>>(scores, post_length, attn, out_attn);

    // Phase D3: context_b = attn_b @ post_b
    tgemm_nn<<<dim3(PDIM / 128, SEQ / 128, BATCH), 256>>>(
        SEQ, PDIM, PLEN,
        attn, PLEN, (long long)SEQ * PLEN,
        post, (long long)BATCH * PDIM, PDIM,
        out_hs + HDIM, (long long)BATCH * 2 * HDIM, 2 * HDIM);
}